// round 9
// baseline (speedup 1.0000x reference)
#include <cuda_runtime.h>
#include <cuda_bf16.h>
#include <math.h>

#define D_MODEL 1024
#define D_KEY   128
#define N_SUB   256
#define TOPK    8
#define MAXNT   8192

// -------- scratch (device globals) --------
__device__ __align__(128) __nv_bfloat16 g_wqb[2 * D_KEY * D_MODEL];
__device__ __align__(128) __nv_bfloat16 g_kb [2 * N_SUB * D_KEY];
__device__ __align__(128) __nv_bfloat16 g_qb [MAXNT * 2 * D_KEY];
__device__ __align__(128) unsigned g_cand[MAXNT * 16];
__device__ float g_wts[MAXNT * TOPK];
__device__ int   g_idx[MAXNT * TOPK];

// ================= base-PTX helpers =================
__device__ __forceinline__ unsigned smem_u32(const void* p) {
    unsigned a;
    asm("{ .reg .u64 t; cvta.to.shared.u64 t, %1; cvt.u32.u64 %0, t; }" : "=r"(a) : "l"(p));
    return a;
}
__device__ __forceinline__ void cpa16(unsigned d, const void* s) {
    asm volatile("cp.async.cg.shared.global [%0], [%1], 16;" :: "r"(d), "l"(s));
}
__device__ __forceinline__ void cpcommit() { asm volatile("cp.async.commit_group;" ::: "memory"); }
template<int N> __device__ __forceinline__ void cpwait() {
    asm volatile("cp.async.wait_group %0;" :: "n"(N) : "memory");
}
__device__ __forceinline__ void ldsm4(unsigned addr, unsigned& r0, unsigned& r1,
                                      unsigned& r2, unsigned& r3) {
    asm volatile("ldmatrix.sync.aligned.m8n8.x4.shared.b16 {%0,%1,%2,%3}, [%4];"
                 : "=r"(r0), "=r"(r1), "=r"(r2), "=r"(r3) : "r"(addr));
}
__device__ __forceinline__ void mma16816(float* c, const unsigned* a, const unsigned* b) {
    asm volatile("mma.sync.aligned.m16n8k16.row.col.f32.bf16.bf16.f32 "
                 "{%0,%1,%2,%3}, {%4,%5,%6,%7}, {%8,%9}, {%0,%1,%2,%3};"
                 : "+f"(c[0]), "+f"(c[1]), "+f"(c[2]), "+f"(c[3])
                 : "r"(a[0]), "r"(a[1]), "r"(a[2]), "r"(a[3]), "r"(b[0]), "r"(b[1]));
}
__device__ __forceinline__ unsigned pk_bf16x2(float a, float b) {
    __nv_bfloat162 h = __floats2bfloat162_rn(a, b);
    return *(unsigned*)&h;
}
__device__ __forceinline__ unsigned fmono(float f) {
    unsigned u = __float_as_uint(f);
    return u ^ (((unsigned)((int)u >> 31)) | 0x80000000u);
}
__device__ __forceinline__ float funmono(unsigned m) {
    unsigned u = (m & 0x80000000u) ? (m ^ 0x80000000u) : ~m;
    return __uint_as_float(u);
}
__device__ __forceinline__ unsigned redux_max(unsigned v) {
    unsigned d;
    asm volatile("redux.sync.max.u32 %0, %1, 0xffffffff;" : "=r"(d) : "r"(v));
    return d;
}

// ================= convert fp32 -> bf16 (Wq, keys only) =================
__global__ __launch_bounds__(256) void convert_small(
    const float4* __restrict__ wq,
    const float4* __restrict__ ka, const float4* __restrict__ kb,
    uint2* __restrict__ wqb, uint2* __restrict__ kbb)
{
    const int W4 = (2 * D_KEY * D_MODEL) / 4;   // 65536
    const int K4 = (N_SUB * D_KEY) / 4;         // 8192
    int i = blockIdx.x * blockDim.x + threadIdx.x;
    float4 v; uint2 o;
    if (i < W4) {
        v = wq[i];
        o.x = pk_bf16x2(v.x, v.y); o.y = pk_bf16x2(v.z, v.w);
        wqb[i] = o;
    } else if (i < W4 + K4) {
        int j = i - W4; v = ka[j];
        o.x = pk_bf16x2(v.x, v.y); o.y = pk_bf16x2(v.z, v.w);
        kbb[j] = o;
    } else if (i < W4 + 2 * K4) {
        int j = i - W4 - K4; v = kb[j];
        o.x = pk_bf16x2(v.x, v.y); o.y = pk_bf16x2(v.z, v.w);
        kbb[K4 + j] = o;
    }
}

// ================= GEMM1: q = x(fp32) @ Wq^T(bf16) -> bf16 =================
// A (x) read as fp32, converted in registers, stored bf16 to smem.
// B via cp.async. 3-stage, BK=32, tile 128x128, 8 warps 64x32.
__global__ __launch_bounds__(256) void hmma_gemm1(
    const float* __restrict__ A, int lda,
    const __nv_bfloat16* __restrict__ B, int ldb,
    __nv_bfloat16* __restrict__ C, int ldc, int K)
{
    __shared__ __align__(128) char smem[3 * 16384];
    const unsigned sbase = smem_u32(smem);

    const int tid = threadIdx.x, lane = tid & 31, wid = tid >> 5;
    const int m0 = blockIdx.x * 128;
    const int n0 = blockIdx.y * 128;

    const float* __restrict__ Ab = A + (size_t)m0 * lda;
    const __nv_bfloat16* __restrict__ Bb = B + (size_t)n0 * ldb;

    const int wm = (wid & 1) * 64;
    const int wn = (wid >> 1) * 32;

    const int rowA = wm + (lane & 15);
    const unsigned swzA = ((unsigned)rowA >> 1) & 3;
    const unsigned aBase = (unsigned)rowA * 64;
    const unsigned aSel = lane >> 4;
    const int rowB = wn + (lane & 7) + ((lane >> 4) << 3);
    const unsigned swzB = ((unsigned)rowB >> 1) & 3;
    const unsigned bBase = (unsigned)rowB * 64;
    const unsigned bSel = (lane >> 3) & 1;

    // per-thread A staging: r = tid>>2 + 0/128... two segments
    const int rA0 = tid >> 2, cA = tid & 3;
    const unsigned soffA0 = (unsigned)rA0 * 64 + (((unsigned)cA ^ (((unsigned)rA0 >> 1) & 3)) << 4);
    const int rA1 = rA0 + 64;
    const unsigned soffA1 = (unsigned)rA1 * 64 + (((unsigned)cA ^ (((unsigned)rA1 >> 1) & 3)) << 4);

    float4 bufA[2][2][2];   // [parity][seg][half]

    float acc[4][4][4];
    #pragma unroll
    for (int mt = 0; mt < 4; mt++)
        #pragma unroll
        for (int nt = 0; nt < 4; nt++)
            #pragma unroll
            for (int e = 0; e < 4; e++) acc[mt][nt][e] = 0.f;

    const int KT = K >> 5;

    auto issueA = [&](int kt) {
        const int kb = kt * 32;
        const int par = kt & 1;
        const float* s0 = Ab + (size_t)rA0 * lda + kb + cA * 8;
        const float* s1 = Ab + (size_t)rA1 * lda + kb + cA * 8;
        bufA[par][0][0] = __ldg((const float4*)s0);
        bufA[par][0][1] = __ldg((const float4*)s0 + 1);
        bufA[par][1][0] = __ldg((const float4*)s1);
        bufA[par][1][1] = __ldg((const float4*)s1 + 1);
    };
    auto storeA = [&](int kt) {
        const int par = kt & 1;
        const int st = kt % 3;
        char* base = smem + st * 16384;
        float4 v0 = bufA[par][0][0], v1 = bufA[par][0][1];
        uint4 o0 = make_uint4(pk_bf16x2(v0.x, v0.y), pk_bf16x2(v0.z, v0.w),
                              pk_bf16x2(v1.x, v1.y), pk_bf16x2(v1.z, v1.w));
        *(uint4*)(base + soffA0) = o0;
        float4 w0 = bufA[par][1][0], w1 = bufA[par][1][1];
        uint4 o1 = make_uint4(pk_bf16x2(w0.x, w0.y), pk_bf16x2(w0.z, w0.w),
                              pk_bf16x2(w1.x, w1.y), pk_bf16x2(w1.z, w1.w));
        *(uint4*)(base + soffA1) = o1;
    };
    auto fillB = [&](int kt, int st) {
        const unsigned base = sbase + st * 16384u + 8192u;
        const int kb = kt * 32;
        #pragma unroll
        for (int u = 0; u < 2; u++) {
            int idx = tid + u * 256;
            int r = idx >> 2, c = idx & 3;
            unsigned soff = (unsigned)r * 64 + (((unsigned)c ^ (((unsigned)r >> 1) & 3)) << 4);
            cpa16(base + soff, Bb + (size_t)r * ldb + kb + c * 8);
        }
    };

    issueA(0); fillB(0, 0); cpcommit();
    issueA(1); fillB(1, 1); cpcommit();
    storeA(0);

    for (int kt = 0; kt < KT; kt++) {
        cpwait<1>();
        __syncthreads();
        int pf = kt + 2;
        if (pf < KT) { issueA(pf); fillB(pf, pf % 3); }
        cpcommit();
        if (kt + 1 < KT) storeA(kt + 1);

        const unsigned As = sbase + (kt % 3) * 16384u;
        const unsigned Bs = As + 8192u;
        #pragma unroll
        for (int kk = 0; kk < 2; kk++) {
            unsigned a[4][4];
            #pragma unroll
            for (int mt = 0; mt < 4; mt++)
                ldsm4(As + aBase + mt * 1024u + ((((unsigned)(kk * 2) + aSel) ^ swzA) << 4),
                      a[mt][0], a[mt][1], a[mt][2], a[mt][3]);
            unsigned b[4][2];
            #pragma unroll
            for (int g = 0; g < 2; g++) {
                unsigned r0, r1, r2, r3;
                ldsm4(Bs + bBase + g * 1024u + ((((unsigned)(kk * 2) + bSel) ^ swzB) << 4),
                      r0, r1, r2, r3);
                b[g * 2][0] = r0; b[g * 2][1] = r1;
                b[g * 2 + 1][0] = r2; b[g * 2 + 1][1] = r3;
            }
            #pragma unroll
            for (int mt = 0; mt < 4; mt++)
                #pragma unroll
                for (int nt = 0; nt < 4; nt++)
                    mma16816(acc[mt][nt], a[mt], b[nt]);
        }
        __syncthreads();
    }

    const int gid = lane >> 2;
    const int tg  = (lane & 3) * 2;
    #pragma unroll
    for (int mt = 0; mt < 4; mt++) {
        int r = m0 + wm + mt * 16 + gid;
        #pragma unroll
        for (int nt = 0; nt < 4; nt++) {
            int col = n0 + wn + nt * 8 + tg;
            *(unsigned*)(C + (size_t)r * ldc + col)       = pk_bf16x2(acc[mt][nt][0], acc[mt][nt][1]);
            *(unsigned*)(C + (size_t)(r + 8) * ldc + col) = pk_bf16x2(acc[mt][nt][2], acc[mt][nt][3]);
        }
    }
}

// ================= GEMM2 + per-half top-8 (tile 128x256, K=128) =================
#define SC_LD 260
__global__ __launch_bounds__(256) void gemm2_topk(
    const __nv_bfloat16* __restrict__ Aq,
    const __nv_bfloat16* __restrict__ Keys,
    unsigned* __restrict__ cand)
{
    extern __shared__ __align__(128) char dsm[];
    const unsigned sbase = smem_u32(dsm);

    const int tid = threadIdx.x, lane = tid & 31, wid = tid >> 5;
    const int m0 = blockIdx.x * 128;
    const int z  = blockIdx.y;

    const __nv_bfloat16* __restrict__ Ab = Aq + (size_t)m0 * (2 * D_KEY) + z * D_KEY;
    const __nv_bfloat16* __restrict__ Bb = Keys + (size_t)z * N_SUB * D_KEY;

    const int wm = (wid & 1) * 64;
    const int wn = (wid >> 1) * 64;

    const int rowA = wm + (lane & 15);
    const unsigned swzA = ((unsigned)rowA >> 1) & 3;
    const unsigned aBase = (unsigned)rowA * 64;
    const unsigned aSel = lane >> 4;
    const int rowB = wn + (lane & 7) + ((lane >> 4) << 3);
    const unsigned swzB = ((unsigned)rowB >> 1) & 3;
    const unsigned bBase = (unsigned)rowB * 64;
    const unsigned bSel = (lane >> 3) & 1;

    float acc[4][8][4];
    #pragma unroll
    for (int mt = 0; mt < 4; mt++)
        #pragma unroll
        for (int nt = 0; nt < 8; nt++)
            #pragma unroll
            for (int e = 0; e < 4; e++) acc[mt][nt][e] = 0.f;

    auto fill = [&](int kt, int st) {
        const unsigned base = sbase + st * 24576u;
        const int kb = kt * 32;
        #pragma unroll
        for (int u = 0; u < 2; u++) {
            int idx = tid + u * 256;
            int r = idx >> 2, c = idx & 3;
            unsigned soff = (unsigned)r * 64 + (((unsigned)c ^ (((unsigned)r >> 1) & 3)) << 4);
            cpa16(base + soff, Ab + (size_t)r * (2 * D_KEY) + kb + c * 8);
        }
        #pragma unroll
        for (int u = 0; u < 4; u++) {
            int idx = tid + u * 256;
            int r = idx >> 2, c = idx & 3;
            unsigned soff = (unsigned)r * 64 + (((unsigned)c ^ (((unsigned)r >> 1) & 3)) << 4);
            cpa16(base + 8192u + soff, Bb + (size_t)r * D_KEY + kb + c * 8);
        }
    };

    const int KT = 4;
    fill(0, 0); cpcommit();
    fill(1, 1); cpcommit();

    for (int kt = 0; kt < KT; kt++) {
        cpwait<1>();
        __syncthreads();
        int pf = kt + 2;
        if (pf < KT) fill(pf, pf % 3);
        cpcommit();

        const unsigned As = sbase + (kt % 3) * 24576u;
        const unsigned Bs = As + 8192u;
        #pragma unroll
        for (int kk = 0; kk < 2; kk++) {
            unsigned a[4][4];
            #pragma unroll
            for (int mt = 0; mt < 4; mt++)
                ldsm4(As + aBase + mt * 1024u + ((((unsigned)(kk * 2) + aSel) ^ swzA) << 4),
                      a[mt][0], a[mt][1], a[mt][2], a[mt][3]);
            unsigned b[8][2];
            #pragma unroll
            for (int g = 0; g < 4; g++) {
                unsigned r0, r1, r2, r3;
                ldsm4(Bs + bBase + g * 1024u + ((((unsigned)(kk * 2) + bSel) ^ swzB) << 4),
                      r0, r1, r2, r3);
                b[g * 2][0] = r0; b[g * 2][1] = r1;
                b[g * 2 + 1][0] = r2; b[g * 2 + 1][1] = r3;
            }
            #pragma unroll
            for (int mt = 0; mt < 4; mt++)
                #pragma unroll
                for (int nt = 0; nt < 8; nt++)
                    mma16816(acc[mt][nt], a[mt], b[nt]);
        }
        __syncthreads();
    }

    // dump accumulators to smem score buffer [128][SC_LD]
    float* sc = (float*)dsm;
    const int gid = lane >> 2;
    const int tg  = (lane & 3) * 2;
    __syncthreads();
    #pragma unroll
    for (int mt = 0; mt < 4; mt++) {
        int r = wm + mt * 16 + gid;
        #pragma unroll
        for (int nt = 0; nt < 8; nt++) {
            int col = wn + nt * 8 + tg;
            *(float2*)&sc[(size_t)r * SC_LD + col]       = make_float2(acc[mt][nt][0], acc[mt][nt][1]);
            *(float2*)&sc[(size_t)(r + 8) * SC_LD + col] = make_float2(acc[mt][nt][2], acc[mt][nt][3]);
        }
    }
    __syncthreads();

    // per-warp top-8, TWO rows interleaved per pass (independent redux chains)
    for (int j = 0; j < 8; j++) {
        const int r0 = wid * 16 + j;
        const int r1 = r0 + 8;
        unsigned k0[8], k1[8];
        #pragma unroll
        for (int s = 0; s < 8; s++) {
            unsigned tag = 255u - (unsigned)(s * 32 + lane);
            k0[s] = (fmono(sc[(size_t)r0 * SC_LD + s * 32 + lane]) & 0xFFFFFF00u) | tag;
            k1[s] = (fmono(sc[(size_t)r1 * SC_LD + s * 32 + lane]) & 0xFFFFFF00u) | tag;
        }
        unsigned my0 = 0u, my1 = 0u;
        #pragma unroll
        for (int it = 0; it < TOPK; it++) {
            unsigned l0 = k0[0], l1 = k1[0];
            #pragma unroll
            for (int s = 1; s < 8; s++) { l0 = max(l0, k0[s]); l1 = max(l1, k1[s]); }
            unsigned w0 = redux_max(l0);
            unsigned w1 = redux_max(l1);
            if (lane == it) { my0 = w0; my1 = w1; }
            #pragma unroll
            for (int s = 0; s < 8; s++) {
                if (k0[s] == w0) k0[s] = 0u;
                if (k1[s] == w1) k1[s] = 0u;
            }
        }
        if (lane < TOPK) {
            cand[(size_t)(m0 + r0) * 16 + z * 8 + lane] = my0;
            cand[(size_t)(m0 + r1) * 16 + z * 8 + lane] = my1;
        }
    }
}

// ================= combine: 64 cartesian candidates -> top-8 + softmax =================
__global__ __launch_bounds__(256) void combine_kernel(
    const unsigned* __restrict__ cand,
    float* __restrict__ wts, int* __restrict__ idxs, int NT)
{
    const unsigned FULL = 0xffffffffu;
    const int lane = threadIdx.x & 31;
    const int t = blockIdx.x * 8 + (threadIdx.x >> 5);
    if (t >= NT) return;
    const unsigned* c = cand + (size_t)t * 16;

    unsigned a0k = __ldg(c + (lane >> 3));
    unsigned a1k = __ldg(c + (lane >> 3) + 4);
    unsigned bk  = __ldg(c + 8 + (lane & 7));
    float bvf = funmono(bk & 0xFFFFFF00u);
    float c0 = funmono(a0k & 0xFFFFFF00u) + bvf;
    float c1 = funmono(a1k & 0xFFFFFF00u) + bvf;
    int ib  = 255 - (int)(bk & 255u);
    int idx0 = (255 - (int)(a0k & 255u)) * N_SUB + ib;
    int idx1 = (255 - (int)(a1k & 255u)) * N_SUB + ib;
    unsigned k0 = (fmono(c0) & ~63u) | (63u - (unsigned)lane);
    unsigned k1 = (fmono(c1) & ~63u) | (63u - (unsigned)(lane + 32));

    unsigned fkey = 0u; int fid = 0;
    #pragma unroll
    for (int it = 0; it < TOPK; it++) {
        unsigned loc = redux_max(max(k0, k1));
        unsigned pos = 63u - (loc & 63u);
        int src = (int)(pos & 31u);
        int widx = (pos < 32u) ? __shfl_sync(FULL, idx0, src)
                               : __shfl_sync(FULL, idx1, src);
        if (lane == it) { fkey = loc; fid = widx; }
        if (k0 == loc) k0 = 0u;
        if (k1 == loc) k1 = 0u;
    }

    float val = funmono(fkey & ~63u);
    float v0 = __shfl_sync(FULL, val, 0);
    float e = (lane < TOPK) ? expf(val - v0) : 0.f;
    float ssum = e;
    #pragma unroll
    for (int off = 4; off; off >>= 1) ssum += __shfl_xor_sync(FULL, ssum, off);
    if (lane < TOPK) {
        wts[(size_t)t * TOPK + lane]  = e / ssum;
        idxs[(size_t)t * TOPK + lane] = fid;
    }
}

// ================= gather: 2 tokens per block, amortized prologue =================
__global__ __launch_bounds__(256) void gather_kernel(
    const float* __restrict__ x, const float* __restrict__ values,
    const float* __restrict__ gate_w, const float* __restrict__ gate_b,
    const float* __restrict__ wts, const int* __restrict__ idxs,
    float* __restrict__ out)
{
    const int t0 = blockIdx.x * 2;
    const int t1 = t0 + 1;
    const int tid = threadIdx.x;
    const int lane = tid & 31, wid = tid >> 5;

    __shared__ float red[2][8];
    __shared__ float sw[2][TOPK];
    __shared__ int   sid[2][TOPK];

    // prologue loads: both tokens' wts/idx via threads 32..63
    if (tid >= 32 && tid < 40)      sw[0][tid - 32] = wts[(size_t)t0 * TOPK + (tid - 32)];
    else if (tid >= 40 && tid < 48) sw[1][tid - 40] = wts[(size_t)t1 * TOPK + (tid - 40)];
    else if (tid >= 48 && tid < 56) sid[0][tid - 48] = idxs[(size_t)t0 * TOPK + (tid - 48)];
    else if (tid >= 56 && tid < 64) sid[1][tid - 56] = idxs[(size_t)t1 * TOPK + (tid - 56)];

    float4 xv0 = ((const float4*)(x + (size_t)t0 * D_MODEL))[tid];
    float4 xv1 = ((const float4*)(x + (size_t)t1 * D_MODEL))[tid];
    float4 gv  = ((const float4*)gate_w)[tid];

    float p0 = xv0.x * gv.x + xv0.y * gv.y + xv0.z * gv.z + xv0.w * gv.w;
    float p1 = xv1.x * gv.x + xv1.y * gv.y + xv1.z * gv.z + xv1.w * gv.w;
    #pragma unroll
    for (int off = 16; off; off >>= 1) {
        p0 += __shfl_down_sync(0xffffffffu, p0, off);
        p1 += __shfl_down_sync(0xffffffffu, p1, off);
    }
    if (lane == 0) { red[0][wid] = p0; red[1][wid] = p1; }
    __syncthreads();

    float s0 = 0.f, s1 = 0.f;
    #pragma unroll
    for (int w = 0; w < 8; w++) { s0 += red[0][w]; s1 += red[1][w]; }
    const float bb = gate_b[0];
    const float g0 = 1.f / (1.f + expf(-(s0 + bb)));
    const float g1 = 1.f / (1.f + expf(-(s1 + bb)));

    float4 a0 = make_float4(0.f, 0.f, 0.f, 0.f);
    float4 a1 = make_float4(0.f, 0.f, 0.f, 0.f);
    #pragma unroll
    for (int k = 0; k < TOPK; k++) {
        float4 v0 = __ldg((const float4*)(values + (size_t)sid[0][k] * D_MODEL) + tid);
        float4 v1 = __ldg((const float4*)(values + (size_t)sid[1][k] * D_MODEL) + tid);
        float w0 = sw[0][k], w1 = sw[1][k];
        a0.x += w0 * v0.x; a0.y += w0 * v0.y; a0.z += w0 * v0.z; a0.w += w0 * v0.w;
        a1.x += w1 * v1.x; a1.y += w1 * v1.y; a1.z += w1 * v1.z; a1.w += w1 * v1.w;
    }
    float4 o0, o1;
    o0.x = xv0.x + g0 * a0.x; o0.y = xv0.y + g0 * a0.y;
    o0.z = xv0.z + g0 * a0.z; o0.w = xv0.w + g0 * a0.w;
    o1.x = xv1.x + g1 * a1.x; o1.y = xv1.y + g1 * a1.y;
    o1.z = xv1.z + g1 * a1.z; o1.w = xv1.w + g1 * a1.w;
    ((float4*)(out + (size_t)t0 * D_MODEL))[tid] = o0;
    ((float4*)(out + (size_t)t1 * D_MODEL))[tid] = o1;
}

// ================= launch =================
extern "C" void kernel_launch(void* const* d_in, const int* in_sizes, int n_in,
                              void* d_out, int out_size)
{
    const float* x      = (const float*)d_in[0];
    const float* keys_a = (const float*)d_in[1];
    const float* keys_b = (const float*)d_in[2];
    const float* values = (const float*)d_in[3];
    const float* Wq     = (const float*)d_in[4];
    const float* gate_w = (const float*)d_in[5];
    const float* gate_b = (const float*)d_in[6];
    float* out = (float*)d_out;

    const int NT = in_sizes[0] / D_MODEL;   // 8192

    __nv_bfloat16 *wqb, *kbb, *qb;
    unsigned* cbuf; float* wbuf; int* ibuf;
    cudaGetSymbolAddress((void**)&wqb,  g_wqb);
    cudaGetSymbolAddress((void**)&kbb,  g_kb);
    cudaGetSymbolAddress((void**)&qb,   g_qb);
    cudaGetSymbolAddress((void**)&cbuf, g_cand);
    cudaGetSymbolAddress((void**)&wbuf, g_wts);
    cudaGetSymbolAddress((void**)&ibuf, g_idx);

    // 0) convert Wq + keys to bf16 (x stays fp32; gemm1 converts on the fly)
    {
        int total = (2 * D_KEY * D_MODEL) / 4 + 2 * (N_SUB * D_KEY) / 4;  // 81920
        convert_small<<<(total + 255) / 256, 256>>>(
            (const float4*)Wq, (const float4*)keys_a, (const float4*)keys_b,
            (uint2*)wqb, (uint2*)kbb);
    }
    // 1) q = x @ Wq^T -> bf16 [NT,256]
    {
        dim3 grid(NT / 128, (2 * D_KEY) / 128);
        hmma_gemm1<<<grid, 256>>>(x, D_MODEL, wqb, D_MODEL, qb, 2 * D_KEY, D_MODEL);
    }
    // 2) scores + per-half top-8 fused
    {
        const int dsm = 128 * SC_LD * 4;   // 133120 >= 3*24576
        cudaFuncSetAttribute(gemm2_topk, cudaFuncAttributeMaxDynamicSharedMemorySize, dsm);
        dim3 grid(NT / 128, 2);
        gemm2_topk<<<grid, 256, dsm>>>(qb, kbb, cbuf);
    }
    // 3) cartesian combine + softmax
    combine_kernel<<<(NT + 7) / 8, 256>>>(cbuf, wbuf, ibuf, NT);
    // 4) gather + gate + residual (2 tokens/block)
    gather_kernel<<<NT / 2, 256>>>(x, values, gate_w, gate_b, wbuf, ibuf, out);
}

// round 10
// speedup vs baseline: 1.1880x; 1.1880x over previous
#include <cuda_runtime.h>
#include <cuda_bf16.h>
#include <math.h>

#define D_MODEL 1024
#define D_KEY   128
#define N_SUB   256
#define TOPK    8
#define MAXNT   8192

// -------- scratch (device globals) --------
__device__ __align__(128) __nv_bfloat16 g_xb [MAXNT * D_MODEL];
__device__ __align__(128) __nv_bfloat16 g_wqb[2 * D_KEY * D_MODEL];
__device__ __align__(128) __nv_bfloat16 g_kb [2 * N_SUB * D_KEY];
__device__ __align__(128) __nv_bfloat16 g_qb [MAXNT * 2 * D_KEY];
__device__ __align__(128) float g_scores[MAXNT * 2 * N_SUB];
__device__ float g_wts[MAXNT * TOPK];
__device__ int   g_idx[MAXNT * TOPK];

// ================= base-PTX helpers =================
__device__ __forceinline__ unsigned smem_u32(const void* p) {
    unsigned a;
    asm("{ .reg .u64 t; cvta.to.shared.u64 t, %1; cvt.u32.u64 %0, t; }" : "=r"(a) : "l"(p));
    return a;
}
__device__ __forceinline__ void cpa16(unsigned d, const void* s) {
    asm volatile("cp.async.cg.shared.global [%0], [%1], 16;" :: "r"(d), "l"(s));
}
__device__ __forceinline__ void cpcommit() { asm volatile("cp.async.commit_group;" ::: "memory"); }
template<int N> __device__ __forceinline__ void cpwait() {
    asm volatile("cp.async.wait_group %0;" :: "n"(N) : "memory");
}
__device__ __forceinline__ void ldsm4(unsigned addr, unsigned& r0, unsigned& r1,
                                      unsigned& r2, unsigned& r3) {
    asm volatile("ldmatrix.sync.aligned.m8n8.x4.shared.b16 {%0,%1,%2,%3}, [%4];"
                 : "=r"(r0), "=r"(r1), "=r"(r2), "=r"(r3) : "r"(addr));
}
__device__ __forceinline__ void mma16816(float* c, const unsigned* a, const unsigned* b) {
    asm volatile("mma.sync.aligned.m16n8k16.row.col.f32.bf16.bf16.f32 "
                 "{%0,%1,%2,%3}, {%4,%5,%6,%7}, {%8,%9}, {%0,%1,%2,%3};"
                 : "+f"(c[0]), "+f"(c[1]), "+f"(c[2]), "+f"(c[3])
                 : "r"(a[0]), "r"(a[1]), "r"(a[2]), "r"(a[3]), "r"(b[0]), "r"(b[1]));
}
__device__ __forceinline__ unsigned pk_bf16x2(float a, float b) {
    __nv_bfloat162 h = __floats2bfloat162_rn(a, b);
    return *(unsigned*)&h;
}
__device__ __forceinline__ unsigned fmono(float f) {
    unsigned u = __float_as_uint(f);
    return u ^ (((unsigned)((int)u >> 31)) | 0x80000000u);
}
__device__ __forceinline__ float funmono(unsigned m) {
    unsigned u = (m & 0x80000000u) ? (m ^ 0x80000000u) : ~m;
    return __uint_as_float(u);
}
__device__ __forceinline__ unsigned redux_max(unsigned v) {
    unsigned d;
    asm volatile("redux.sync.max.u32 %0, %1, 0xffffffff;" : "=r"(d) : "r"(v));
    return d;
}

// ================= convert fp32 -> bf16 (x, Wq, keys) =================
__global__ __launch_bounds__(256) void convert_kernel(
    const float4* __restrict__ x, const float4* __restrict__ wq,
    const float4* __restrict__ ka, const float4* __restrict__ kb,
    uint2* __restrict__ xb, uint2* __restrict__ wqb, uint2* __restrict__ kbb,
    int X4)
{
    const int W4 = (2 * D_KEY * D_MODEL) / 4;
    const int K4 = (N_SUB * D_KEY) / 4;
    int i = blockIdx.x * blockDim.x + threadIdx.x;
    float4 v; uint2 o;
    if (i < X4) {
        v = x[i];
        o.x = pk_bf16x2(v.x, v.y); o.y = pk_bf16x2(v.z, v.w);
        xb[i] = o;
    } else if (i < X4 + W4) {
        int j = i - X4; v = wq[j];
        o.x = pk_bf16x2(v.x, v.y); o.y = pk_bf16x2(v.z, v.w);
        wqb[j] = o;
    } else if (i < X4 + W4 + K4) {
        int j = i - X4 - W4; v = ka[j];
        o.x = pk_bf16x2(v.x, v.y); o.y = pk_bf16x2(v.z, v.w);
        kbb[j] = o;
    } else if (i < X4 + W4 + 2 * K4) {
        int j = i - X4 - W4 - K4; v = kb[j];
        o.x = pk_bf16x2(v.x, v.y); o.y = pk_bf16x2(v.z, v.w);
        kbb[K4 + j] = o;
    }
}

// ================= HMMA GEMM (proven R4-R6) =================
template<bool OUTBF16>
__global__ __launch_bounds__(256) void hmma_gemm(
    const __nv_bfloat16* __restrict__ A, int lda, int aoff_step,
    const __nv_bfloat16* __restrict__ B0, const __nv_bfloat16* __restrict__ B1, int ldb,
    void* __restrict__ Cv, int ldc, int coff_step, int K)
{
    __shared__ __align__(128) char smem[3 * 16384];
    const unsigned sbase = smem_u32(smem);

    const int tid = threadIdx.x, lane = tid & 31, wid = tid >> 5;
    const int m0 = blockIdx.x * 128;
    const int n0 = blockIdx.y * 128;
    const int z  = blockIdx.z;
    const int aoff = z * aoff_step;
    const int coff = z * coff_step;

    const __nv_bfloat16* __restrict__ Ab = A + (size_t)m0 * lda + aoff;
    const __nv_bfloat16* __restrict__ Bb = (z ? B1 : B0) + (size_t)n0 * ldb;

    const int wm = (wid & 1) * 64;
    const int wn = (wid >> 1) * 32;

    const int rowA = wm + (lane & 15);
    const unsigned swzA = ((unsigned)rowA >> 1) & 3;
    const unsigned aBase = (unsigned)rowA * 64;
    const unsigned aSel = lane >> 4;
    const int rowB = wn + (lane & 7) + ((lane >> 4) << 3);
    const unsigned swzB = ((unsigned)rowB >> 1) & 3;
    const unsigned bBase = (unsigned)rowB * 64;
    const unsigned bSel = (lane >> 3) & 1;

    float acc[4][4][4];
    #pragma unroll
    for (int mt = 0; mt < 4; mt++)
        #pragma unroll
        for (int nt = 0; nt < 4; nt++)
            #pragma unroll
            for (int e = 0; e < 4; e++) acc[mt][nt][e] = 0.f;

    const int KT = K >> 5;

    auto fill = [&](int kt, int st) {
        const unsigned base = sbase + st * 16384u;
        const int kb = kt * 32;
        #pragma unroll
        for (int u = 0; u < 2; u++) {
            int idx = tid + u * 256;
            int r = idx >> 2, c = idx & 3;
            unsigned soff = (unsigned)r * 64 + (((unsigned)c ^ (((unsigned)r >> 1) & 3)) << 4);
            cpa16(base + soff,         Ab + (size_t)r * lda + kb + c * 8);
            cpa16(base + 8192u + soff, Bb + (size_t)r * ldb + kb + c * 8);
        }
    };

    fill(0, 0); cpcommit();
    if (KT > 1) fill(1, 1);
    cpcommit();

    for (int kt = 0; kt < KT; kt++) {
        cpwait<1>();
        __syncthreads();
        int pf = kt + 2;
        if (pf < KT) fill(pf, pf % 3);
        cpcommit();

        const unsigned As = sbase + (kt % 3) * 16384u;
        const unsigned Bs = As + 8192u;
        #pragma unroll
        for (int kk = 0; kk < 2; kk++) {
            unsigned a[4][4];
            #pragma unroll
            for (int mt = 0; mt < 4; mt++)
                ldsm4(As + aBase + mt * 1024u + ((((unsigned)(kk * 2) + aSel) ^ swzA) << 4),
                      a[mt][0], a[mt][1], a[mt][2], a[mt][3]);
            unsigned b[4][2];
            #pragma unroll
            for (int g = 0; g < 2; g++) {
                unsigned r0, r1, r2, r3;
                ldsm4(Bs + bBase + g * 1024u + ((((unsigned)(kk * 2) + bSel) ^ swzB) << 4),
                      r0, r1, r2, r3);
                b[g * 2][0] = r0; b[g * 2][1] = r1;
                b[g * 2 + 1][0] = r2; b[g * 2 + 1][1] = r3;
            }
            #pragma unroll
            for (int mt = 0; mt < 4; mt++)
                #pragma unroll
                for (int nt = 0; nt < 4; nt++)
                    mma16816(acc[mt][nt], a[mt], b[nt]);
        }
        __syncthreads();
    }

    const int gid = lane >> 2;
    const int tg  = (lane & 3) * 2;
    if (OUTBF16) {
        __nv_bfloat16* C = (__nv_bfloat16*)Cv;
        #pragma unroll
        for (int mt = 0; mt < 4; mt++) {
            int r = m0 + wm + mt * 16 + gid;
            #pragma unroll
            for (int nt = 0; nt < 4; nt++) {
                int col = coff + n0 + wn + nt * 8 + tg;
                *(unsigned*)(C + (size_t)r * ldc + col)       = pk_bf16x2(acc[mt][nt][0], acc[mt][nt][1]);
                *(unsigned*)(C + (size_t)(r + 8) * ldc + col) = pk_bf16x2(acc[mt][nt][2], acc[mt][nt][3]);
            }
        }
    } else {
        float* C = (float*)Cv;
        #pragma unroll
        for (int mt = 0; mt < 4; mt++) {
            int r = m0 + wm + mt * 16 + gid;
            #pragma unroll
            for (int nt = 0; nt < 4; nt++) {
                int col = coff + n0 + wn + nt * 8 + tg;
                *(float2*)(C + (size_t)r * ldc + col)       = make_float2(acc[mt][nt][0], acc[mt][nt][1]);
                *(float2*)(C + (size_t)(r + 8) * ldc + col) = make_float2(acc[mt][nt][2], acc[mt][nt][3]);
            }
        }
    }
}

// ================= warp-per-token top-k: packed keys + redux.sync (R6) =================
__global__ __launch_bounds__(256) void topk_warp(
    const float* __restrict__ scores,
    float* __restrict__ wts, int* __restrict__ idxs, int NT)
{
    const unsigned FULL = 0xffffffffu;
    const int lane = threadIdx.x & 31;
    const int t = blockIdx.x * 8 + (threadIdx.x >> 5);
    if (t >= NT) return;
    const float* row = scores + (size_t)t * (2 * N_SUB);

    unsigned ka[8], kb[8];
    {
        float4 p0 = *(const float4*)(row + lane * 8);
        float4 p1 = *(const float4*)(row + lane * 8 + 4);
        float4 q0 = *(const float4*)(row + 256 + lane * 8);
        float4 q1 = *(const float4*)(row + 256 + lane * 8 + 4);
        float fa[8] = {p0.x, p0.y, p0.z, p0.w, p1.x, p1.y, p1.z, p1.w};
        float fb[8] = {q0.x, q0.y, q0.z, q0.w, q1.x, q1.y, q1.z, q1.w};
        #pragma unroll
        for (int s = 0; s < 8; s++) {
            unsigned tag = 255u - (unsigned)(lane * 8 + s);
            ka[s] = (fmono(fa[s]) & 0xFFFFFF00u) | tag;
            kb[s] = (fmono(fb[s]) & 0xFFFFFF00u) | tag;
        }
    }

    unsigned myA = 0u, myB = 0u;
    #pragma unroll
    for (int it = 0; it < TOPK; it++) {
        unsigned la = ka[0], lb = kb[0];
        #pragma unroll
        for (int s = 1; s < 8; s++) { la = max(la, ka[s]); lb = max(lb, kb[s]); }
        unsigned wa = redux_max(la);
        unsigned wb = redux_max(lb);
        if (lane == it) { myA = wa; myB = wb; }
        #pragma unroll
        for (int s = 0; s < 8; s++) {
            if (ka[s] == wa) ka[s] = 0u;
            if (kb[s] == wb) kb[s] = 0u;
        }
    }

    unsigned a0k = __shfl_sync(FULL, myA, lane >> 3);
    unsigned a1k = __shfl_sync(FULL, myA, (lane >> 3) + 4);
    unsigned bk  = __shfl_sync(FULL, myB, lane & 7);
    float bvf = funmono(bk & 0xFFFFFF00u);
    float c0 = funmono(a0k & 0xFFFFFF00u) + bvf;
    float c1 = funmono(a1k & 0xFFFFFF00u) + bvf;
    int ib  = 255 - (int)(bk & 255u);
    int idx0 = (255 - (int)(a0k & 255u)) * N_SUB + ib;
    int idx1 = (255 - (int)(a1k & 255u)) * N_SUB + ib;
    unsigned k0 = (fmono(c0) & ~63u) | (63u - (unsigned)lane);
    unsigned k1 = (fmono(c1) & ~63u) | (63u - (unsigned)(lane + 32));

    unsigned fkey = 0u; int fid = 0;
    #pragma unroll
    for (int it = 0; it < TOPK; it++) {
        unsigned loc = redux_max(max(k0, k1));
        unsigned pos = 63u - (loc & 63u);
        int src = (int)(pos & 31u);
        int widx = (pos < 32u) ? __shfl_sync(FULL, idx0, src)
                               : __shfl_sync(FULL, idx1, src);
        if (lane == it) { fkey = loc; fid = widx; }
        if (k0 == loc) k0 = 0u;
        if (k1 == loc) k1 = 0u;
    }

    float val = funmono(fkey & ~63u);
    float v0 = __shfl_sync(FULL, val, 0);
    float e = (lane < TOPK) ? expf(val - v0) : 0.f;
    float ssum = e;
    #pragma unroll
    for (int off = 4; off; off >>= 1) ssum += __shfl_xor_sync(FULL, ssum, off);
    if (lane < TOPK) {
        wts[(size_t)t * TOPK + lane]  = e / ssum;
        idxs[(size_t)t * TOPK + lane] = fid;
    }
}

// ================= gather + gate + residual: batched loads for MLP =================
__global__ __launch_bounds__(256) void gather_kernel(
    const float* __restrict__ x, const float* __restrict__ values,
    const float* __restrict__ gate_w, const float* __restrict__ gate_b,
    const float* __restrict__ wts, const int* __restrict__ idxs,
    float* __restrict__ out)
{
    const int t = blockIdx.x;
    const int tid = threadIdx.x;
    const int lane = tid & 31, wid = tid >> 5;

    const float4* xr = (const float4*)(x + (size_t)t * D_MODEL);
    const float4* gw = (const float4*)gate_w;

    float4 xv = xr[tid];
    float4 gv = gw[tid];
    float p = xv.x * gv.x + xv.y * gv.y + xv.z * gv.z + xv.w * gv.w;
    #pragma unroll
    for (int off = 16; off; off >>= 1) p += __shfl_down_sync(0xffffffffu, p, off);

    __shared__ float red[8];
    __shared__ float sw[TOPK];
    __shared__ int   sid[TOPK];
    __shared__ float sg;
    if (lane == 0) red[wid] = p;
    if (tid >= 32 && tid < 32 + TOPK) {
        sw[tid - 32]  = wts[(size_t)t * TOPK + (tid - 32)];
        sid[tid - 32] = idxs[(size_t)t * TOPK + (tid - 32)];
    }
    __syncthreads();
    if (tid == 0) {
        float s = red[0];
        #pragma unroll
        for (int w = 1; w < 8; w++) s += red[w];
        sg = 1.f / (1.f + expf(-(s + gate_b[0])));
    }
    __syncthreads();
    const float g = sg;

    // batch all 8 row loads (8 independent LDG.128 in flight), then tree-accumulate
    float4 v[TOPK];
    #pragma unroll
    for (int k = 0; k < TOPK; k++)
        v[k] = __ldg((const float4*)(values + (size_t)sid[k] * D_MODEL) + tid);

    float4 s01, s23, s45, s67;
    s01.x = sw[0]*v[0].x + sw[1]*v[1].x; s01.y = sw[0]*v[0].y + sw[1]*v[1].y;
    s01.z = sw[0]*v[0].z + sw[1]*v[1].z; s01.w = sw[0]*v[0].w + sw[1]*v[1].w;
    s23.x = sw[2]*v[2].x + sw[3]*v[3].x; s23.y = sw[2]*v[2].y + sw[3]*v[3].y;
    s23.z = sw[2]*v[2].z + sw[3]*v[3].z; s23.w = sw[2]*v[2].w + sw[3]*v[3].w;
    s45.x = sw[4]*v[4].x + sw[5]*v[5].x; s45.y = sw[4]*v[4].y + sw[5]*v[5].y;
    s45.z = sw[4]*v[4].z + sw[5]*v[5].z; s45.w = sw[4]*v[4].w + sw[5]*v[5].w;
    s67.x = sw[6]*v[6].x + sw[7]*v[7].x; s67.y = sw[6]*v[6].y + sw[7]*v[7].y;
    s67.z = sw[6]*v[6].z + sw[7]*v[7].z; s67.w = sw[6]*v[6].w + sw[7]*v[7].w;

    float4 acc;
    acc.x = (s01.x + s23.x) + (s45.x + s67.x);
    acc.y = (s01.y + s23.y) + (s45.y + s67.y);
    acc.z = (s01.z + s23.z) + (s45.z + s67.z);
    acc.w = (s01.w + s23.w) + (s45.w + s67.w);

    float4 o;
    o.x = xv.x + g * acc.x;
    o.y = xv.y + g * acc.y;
    o.z = xv.z + g * acc.z;
    o.w = xv.w + g * acc.w;
    ((float4*)(out + (size_t)t * D_MODEL))[tid] = o;
}

// ================= launch =================
extern "C" void kernel_launch(void* const* d_in, const int* in_sizes, int n_in,
                              void* d_out, int out_size)
{
    const float* x      = (const float*)d_in[0];
    const float* keys_a = (const float*)d_in[1];
    const float* keys_b = (const float*)d_in[2];
    const float* values = (const float*)d_in[3];
    const float* Wq     = (const float*)d_in[4];
    const float* gate_w = (const float*)d_in[5];
    const float* gate_b = (const float*)d_in[6];
    float* out = (float*)d_out;

    const int NT = in_sizes[0] / D_MODEL;   // 8192

    __nv_bfloat16 *xb, *wqb, *kbb, *qb;
    float *sbuf, *wbuf; int *ibuf;
    cudaGetSymbolAddress((void**)&xb,   g_xb);
    cudaGetSymbolAddress((void**)&wqb,  g_wqb);
    cudaGetSymbolAddress((void**)&kbb,  g_kb);
    cudaGetSymbolAddress((void**)&qb,   g_qb);
    cudaGetSymbolAddress((void**)&sbuf, g_scores);
    cudaGetSymbolAddress((void**)&wbuf, g_wts);
    cudaGetSymbolAddress((void**)&ibuf, g_idx);

    // 0) convert inputs to bf16
    {
        int X4 = NT * D_MODEL / 4;
        int total = X4 + (2 * D_KEY * D_MODEL) / 4 + 2 * (N_SUB * D_KEY) / 4;
        convert_kernel<<<(total + 255) / 256, 256>>>(
            (const float4*)x, (const float4*)Wq, (const float4*)keys_a, (const float4*)keys_b,
            (uint2*)xb, (uint2*)wqb, (uint2*)kbb, X4);
    }
    // 1) q = x @ Wq^T -> bf16 [NT,256]
    {
        dim3 grid(NT / 128, (2 * D_KEY) / 128, 1);
        hmma_gemm<true><<<grid, 256>>>(xb, D_MODEL, 0, wqb, wqb, D_MODEL,
                                       qb, 2 * D_KEY, 0, D_MODEL);
    }
    // 2) scores = q @ keys^T (both halves via grid.z) -> fp32 [NT,512]
    {
        dim3 grid(NT / 128, N_SUB / 128, 2);
        hmma_gemm<false><<<grid, 256>>>(qb, 2 * D_KEY, D_KEY,
                                        kbb, kbb + N_SUB * D_KEY, D_KEY,
                                        sbuf, 2 * N_SUB, N_SUB, D_KEY);
    }
    // 3) top-k + softmax
    topk_warp<<<(NT + 7) / 8, 256>>>(sbuf, wbuf, ibuf, NT);
    // 4) gather + gate + residual
    gather_kernel<<<NT, 256>>>(x, values, gate_w, gate_b, wbuf, ibuf, out);
}

// round 11
// speedup vs baseline: 1.2932x; 1.0886x over previous
#include <cuda_runtime.h>
#include <cuda_bf16.h>
#include <math.h>

#define D_MODEL 1024
#define D_KEY   128
#define N_SUB   256
#define TOPK    8
#define MAXNT   8192

// -------- scratch (device globals) --------
__device__ __align__(128) __nv_bfloat16 g_xb [MAXNT * D_MODEL];
__device__ __align__(128) __nv_bfloat16 g_wqb[2 * D_KEY * D_MODEL];
__device__ __align__(128) __nv_bfloat16 g_kb [2 * N_SUB * D_KEY];
__device__ __align__(128) float g_scores[MAXNT * 2 * N_SUB];
__device__ float g_wts[MAXNT * TOPK];
__device__ int   g_idx[MAXNT * TOPK];

// ================= base-PTX helpers =================
__device__ __forceinline__ unsigned smem_u32(const void* p) {
    unsigned a;
    asm("{ .reg .u64 t; cvta.to.shared.u64 t, %1; cvt.u32.u64 %0, t; }" : "=r"(a) : "l"(p));
    return a;
}
__device__ __forceinline__ void cpa16(unsigned d, const void* s) {
    asm volatile("cp.async.cg.shared.global [%0], [%1], 16;" :: "r"(d), "l"(s));
}
__device__ __forceinline__ void cpcommit() { asm volatile("cp.async.commit_group;" ::: "memory"); }
template<int N> __device__ __forceinline__ void cpwait() {
    asm volatile("cp.async.wait_group %0;" :: "n"(N) : "memory");
}
__device__ __forceinline__ void ldsm4(unsigned addr, unsigned& r0, unsigned& r1,
                                      unsigned& r2, unsigned& r3) {
    asm volatile("ldmatrix.sync.aligned.m8n8.x4.shared.b16 {%0,%1,%2,%3}, [%4];"
                 : "=r"(r0), "=r"(r1), "=r"(r2), "=r"(r3) : "r"(addr));
}
__device__ __forceinline__ void mma16816(float* c, const unsigned* a, const unsigned* b) {
    asm volatile("mma.sync.aligned.m16n8k16.row.col.f32.bf16.bf16.f32 "
                 "{%0,%1,%2,%3}, {%4,%5,%6,%7}, {%8,%9}, {%0,%1,%2,%3};"
                 : "+f"(c[0]), "+f"(c[1]), "+f"(c[2]), "+f"(c[3])
                 : "r"(a[0]), "r"(a[1]), "r"(a[2]), "r"(a[3]), "r"(b[0]), "r"(b[1]));
}
__device__ __forceinline__ unsigned pk_bf16x2(float a, float b) {
    __nv_bfloat162 h = __floats2bfloat162_rn(a, b);
    return *(unsigned*)&h;
}
__device__ __forceinline__ unsigned fmono(float f) {
    unsigned u = __float_as_uint(f);
    return u ^ (((unsigned)((int)u >> 31)) | 0x80000000u);
}
__device__ __forceinline__ float funmono(unsigned m) {
    unsigned u = (m & 0x80000000u) ? (m ^ 0x80000000u) : ~m;
    return __uint_as_float(u);
}
__device__ __forceinline__ unsigned redux_max(unsigned v) {
    unsigned d;
    asm volatile("redux.sync.max.u32 %0, %1, 0xffffffff;" : "=r"(d) : "r"(v));
    return d;
}

// ================= convert fp32 -> bf16 (x, Wq, keys) =================
__global__ __launch_bounds__(256) void convert_kernel(
    const float4* __restrict__ x, const float4* __restrict__ wq,
    const float4* __restrict__ ka, const float4* __restrict__ kb,
    uint2* __restrict__ xb, uint2* __restrict__ wqb, uint2* __restrict__ kbb,
    int X4)
{
    const int W4 = (2 * D_KEY * D_MODEL) / 4;
    const int K4 = (N_SUB * D_KEY) / 4;
    int i = blockIdx.x * blockDim.x + threadIdx.x;
    float4 v; uint2 o;
    if (i < X4) {
        v = x[i];
        o.x = pk_bf16x2(v.x, v.y); o.y = pk_bf16x2(v.z, v.w);
        xb[i] = o;
    } else if (i < X4 + W4) {
        int j = i - X4; v = wq[j];
        o.x = pk_bf16x2(v.x, v.y); o.y = pk_bf16x2(v.z, v.w);
        wqb[j] = o;
    } else if (i < X4 + W4 + K4) {
        int j = i - X4 - W4; v = ka[j];
        o.x = pk_bf16x2(v.x, v.y); o.y = pk_bf16x2(v.z, v.w);
        kbb[j] = o;
    } else if (i < X4 + W4 + 2 * K4) {
        int j = i - X4 - W4 - K4; v = kb[j];
        o.x = pk_bf16x2(v.x, v.y); o.y = pk_bf16x2(v.z, v.w);
        kbb[K4 + j] = o;
    }
}

// ================= fused GEMM1+GEMM2: block (mx, z) =================
// Phase A: q tile [128 rows x 128 cols] = xb[m0:,:] @ Wq_z^T, K=1024, 3-stage cp.async.
// q tile stored bf16 into chunk-swizzled smem (the A-operand layout of phase B).
// Phase B: scores [128 x 256] = qtile @ keys_z^T, K=128, keys prefetched early.
// Smem: [0,49152) pipeline (A 8KB + B 8KB per stage x3); qtile reuses [0,32768);
//       [49152, 114688) keys (4 chunks x 16KB).
__global__ __launch_bounds__(256) void fused_gemm(
    const __nv_bfloat16* __restrict__ Xb,
    const __nv_bfloat16* __restrict__ Wqb,
    const __nv_bfloat16* __restrict__ Keys,
    float* __restrict__ S)
{
    extern __shared__ __align__(128) char dsm[];
    const unsigned sbase = smem_u32(dsm);
    const unsigned KB = sbase + 49152u;

    const int tid = threadIdx.x, lane = tid & 31, wid = tid >> 5;
    const int m0 = blockIdx.x * 128;
    const int z  = blockIdx.y;

    const __nv_bfloat16* __restrict__ Ab = Xb + (size_t)m0 * D_MODEL;
    const __nv_bfloat16* __restrict__ Bb = Wqb + (size_t)(z * D_KEY) * D_MODEL;
    const __nv_bfloat16* __restrict__ Kz = Keys + (size_t)z * N_SUB * D_KEY;

    // ---------- phase A warp layout (64x32 warp tiles) ----------
    const int wmA = (wid & 1) * 64;
    const int wnA = (wid >> 1) * 32;
    const int rowA = wmA + (lane & 15);
    const unsigned swzA = ((unsigned)rowA >> 1) & 3;
    const unsigned aBase = (unsigned)rowA * 64;
    const unsigned aSel = lane >> 4;
    const int rowB = wnA + (lane & 7) + ((lane >> 4) << 3);
    const unsigned swzB = ((unsigned)rowB >> 1) & 3;
    const unsigned bBase = (unsigned)rowB * 64;
    const unsigned bSel = (lane >> 3) & 1;

    float acc[4][4][4];
    #pragma unroll
    for (int mt = 0; mt < 4; mt++)
        #pragma unroll
        for (int nt = 0; nt < 4; nt++)
            #pragma unroll
            for (int e = 0; e < 4; e++) acc[mt][nt][e] = 0.f;

    auto fill = [&](int kt, int st) {
        const unsigned base = sbase + st * 16384u;
        const int kb = kt * 32;
        #pragma unroll
        for (int u = 0; u < 2; u++) {
            int idx = tid + u * 256;
            int r = idx >> 2, c = idx & 3;
            unsigned soff = (unsigned)r * 64 + (((unsigned)c ^ (((unsigned)r >> 1) & 3)) << 4);
            cpa16(base + soff,         Ab + (size_t)r * D_MODEL + kb + c * 8);
            cpa16(base + 8192u + soff, Bb + (size_t)r * D_MODEL + kb + c * 8);
        }
    };

    // prefill stages 0,1; then keys as their own group (off critical path via wait<2>)
    fill(0, 0); cpcommit();
    fill(1, 1); cpcommit();
    #pragma unroll
    for (int i = 0; i < 16; i++) {
        int idx = tid + i * 256;          // 0..4095: 4 chunks x 256 rows x 4 units
        int c = idx >> 10;
        int r = (idx >> 2) & 255;
        int u = idx & 3;
        cpa16(KB + (unsigned)c * 16384u + (unsigned)r * 64u +
                  ((((unsigned)u) ^ (((unsigned)r >> 1) & 3)) << 4),
              Kz + (size_t)r * D_KEY + c * 32 + u * 8);
    }
    cpcommit();

    const int KT = 32;   // K=1024
    for (int kt = 0; kt < KT; kt++) {
        cpwait<2>();
        __syncthreads();
        int pf = kt + 2;
        if (pf < KT) fill(pf, pf % 3);
        cpcommit();

        const unsigned As = sbase + (kt % 3) * 16384u;
        const unsigned Bs = As + 8192u;
        #pragma unroll
        for (int kk = 0; kk < 2; kk++) {
            unsigned a[4][4];
            #pragma unroll
            for (int mt = 0; mt < 4; mt++)
                ldsm4(As + aBase + mt * 1024u + ((((unsigned)(kk * 2) + aSel) ^ swzA) << 4),
                      a[mt][0], a[mt][1], a[mt][2], a[mt][3]);
            unsigned b[4][2];
            #pragma unroll
            for (int g = 0; g < 2; g++) {
                unsigned r0, r1, r2, r3;
                ldsm4(Bs + bBase + g * 1024u + ((((unsigned)(kk * 2) + bSel) ^ swzB) << 4),
                      r0, r1, r2, r3);
                b[g * 2][0] = r0; b[g * 2][1] = r1;
                b[g * 2 + 1][0] = r2; b[g * 2 + 1][1] = r3;
            }
            #pragma unroll
            for (int mt = 0; mt < 4; mt++)
                #pragma unroll
                for (int nt = 0; nt < 4; nt++)
                    mma16816(acc[mt][nt], a[mt], b[nt]);
        }
        __syncthreads();
    }

    // ---------- epilogue A: q tile -> smem [0,32768), chunked + swizzled bf16 ----------
    const int gid = lane >> 2;
    const int tg  = (lane & 3) * 2;
    #pragma unroll
    for (int mt = 0; mt < 4; mt++) {
        int r  = wmA + mt * 16 + gid;
        int r2 = r + 8;
        #pragma unroll
        for (int nt = 0; nt < 4; nt++) {
            int c = wnA + nt * 8 + tg;
            unsigned chunk = (unsigned)c >> 5, within = (unsigned)c & 31;
            unsigned u = within >> 3;
            unsigned byteoff0 = chunk * 8192u + (unsigned)r * 64u +
                                ((u ^ (((unsigned)r >> 1) & 3)) << 4) + (within & 7) * 2;
            unsigned byteoff1 = chunk * 8192u + (unsigned)r2 * 64u +
                                ((u ^ (((unsigned)r2 >> 1) & 3)) << 4) + (within & 7) * 2;
            *(unsigned*)(dsm + byteoff0) = pk_bf16x2(acc[mt][nt][0], acc[mt][nt][1]);
            *(unsigned*)(dsm + byteoff1) = pk_bf16x2(acc[mt][nt][2], acc[mt][nt][3]);
        }
    }
    cpwait<0>();      // keys resident
    __syncthreads();

    // ---------- phase B: scores = qtile @ keys_z^T (128x256, K=128) ----------
    const int wmB = (wid & 1) * 64;
    const int wnB = (wid >> 1) * 64;
    const int rowA2 = wmB + (lane & 15);
    const unsigned swzA2 = ((unsigned)rowA2 >> 1) & 3;
    const unsigned aBase2 = (unsigned)rowA2 * 64;
    const int rowB2 = wnB + (lane & 7) + ((lane >> 4) << 3);
    const unsigned swzB2 = ((unsigned)rowB2 >> 1) & 3;
    const unsigned bBase2 = (unsigned)rowB2 * 64;

    float acc2[4][8][4];
    #pragma unroll
    for (int mt = 0; mt < 4; mt++)
        #pragma unroll
        for (int nt = 0; nt < 8; nt++)
            #pragma unroll
            for (int e = 0; e < 4; e++) acc2[mt][nt][e] = 0.f;

    #pragma unroll
    for (int k = 0; k < 4; k++) {
        const unsigned As = sbase + (unsigned)k * 8192u;
        const unsigned Bs = KB + (unsigned)k * 16384u;
        #pragma unroll
        for (int kk = 0; kk < 2; kk++) {
            unsigned a[4][4];
            #pragma unroll
            for (int mt = 0; mt < 4; mt++)
                ldsm4(As + aBase2 + mt * 1024u + ((((unsigned)(kk * 2) + aSel) ^ swzA2) << 4),
                      a[mt][0], a[mt][1], a[mt][2], a[mt][3]);
            unsigned b[8][2];
            #pragma unroll
            for (int g = 0; g < 4; g++) {
                unsigned r0, r1, r2, r3;
                ldsm4(Bs + bBase2 + g * 1024u + ((((unsigned)(kk * 2) + bSel) ^ swzB2) << 4),
                      r0, r1, r2, r3);
                b[g * 2][0] = r0; b[g * 2][1] = r1;
                b[g * 2 + 1][0] = r2; b[g * 2 + 1][1] = r3;
            }
            #pragma unroll
            for (int mt = 0; mt < 4; mt++)
                #pragma unroll
                for (int nt = 0; nt < 8; nt++)
                    mma16816(acc2[mt][nt], a[mt], b[nt]);
        }
    }

    // ---------- epilogue B: fp32 scores to gmem ----------
    #pragma unroll
    for (int mt = 0; mt < 4; mt++) {
        int r = m0 + wmB + mt * 16 + gid;
        #pragma unroll
        for (int nt = 0; nt < 8; nt++) {
            int col = z * N_SUB + wnB + nt * 8 + tg;
            *(float2*)(S + (size_t)r * (2 * N_SUB) + col)       = make_float2(acc2[mt][nt][0], acc2[mt][nt][1]);
            *(float2*)(S + (size_t)(r + 8) * (2 * N_SUB) + col) = make_float2(acc2[mt][nt][2], acc2[mt][nt][3]);
        }
    }
}

// ================= warp-per-token top-k: packed keys + redux.sync (exact R6) =================
__global__ __launch_bounds__(256) void topk_warp(
    const float* __restrict__ scores,
    float* __restrict__ wts, int* __restrict__ idxs, int NT)
{
    const unsigned FULL = 0xffffffffu;
    const int lane = threadIdx.x & 31;
    const int t = blockIdx.x * 8 + (threadIdx.x >> 5);
    if (t >= NT) return;
    const float* row = scores + (size_t)t * (2 * N_SUB);

    unsigned ka[8], kb[8];
    {
        float4 p0 = *(const float4*)(row + lane * 8);
        float4 p1 = *(const float4*)(row + lane * 8 + 4);
        float4 q0 = *(const float4*)(row + 256 + lane * 8);
        float4 q1 = *(const float4*)(row + 256 + lane * 8 + 4);
        float fa[8] = {p0.x, p0.y, p0.z, p0.w, p1.x, p1.y, p1.z, p1.w};
        float fb[8] = {q0.x, q0.y, q0.z, q0.w, q1.x, q1.y, q1.z, q1.w};
        #pragma unroll
        for (int s = 0; s < 8; s++) {
            unsigned tag = 255u - (unsigned)(lane * 8 + s);
            ka[s] = (fmono(fa[s]) & 0xFFFFFF00u) | tag;
            kb[s] = (fmono(fb[s]) & 0xFFFFFF00u) | tag;
        }
    }

    unsigned myA = 0u, myB = 0u;
    #pragma unroll
    for (int it = 0; it < TOPK; it++) {
        unsigned la = ka[0], lb = kb[0];
        #pragma unroll
        for (int s = 1; s < 8; s++) { la = max(la, ka[s]); lb = max(lb, kb[s]); }
        unsigned wa = redux_max(la);
        unsigned wb = redux_max(lb);
        if (lane == it) { myA = wa; myB = wb; }
        #pragma unroll
        for (int s = 0; s < 8; s++) {
            if (ka[s] == wa) ka[s] = 0u;
            if (kb[s] == wb) kb[s] = 0u;
        }
    }

    unsigned a0k = __shfl_sync(FULL, myA, lane >> 3);
    unsigned a1k = __shfl_sync(FULL, myA, (lane >> 3) + 4);
    unsigned bk  = __shfl_sync(FULL, myB, lane & 7);
    float bvf = funmono(bk & 0xFFFFFF00u);
    float c0 = funmono(a0k & 0xFFFFFF00u) + bvf;
    float c1 = funmono(a1k & 0xFFFFFF00u) + bvf;
    int ib  = 255 - (int)(bk & 255u);
    int idx0 = (255 - (int)(a0k & 255u)) * N_SUB + ib;
    int idx1 = (255 - (int)(a1k & 255u)) * N_SUB + ib;
    unsigned k0 = (fmono(c0) & ~63u) | (63u - (unsigned)lane);
    unsigned k1 = (fmono(c1) & ~63u) | (63u - (unsigned)(lane + 32));

    unsigned fkey = 0u; int fid = 0;
    #pragma unroll
    for (int it = 0; it < TOPK; it++) {
        unsigned loc = redux_max(max(k0, k1));
        unsigned pos = 63u - (loc & 63u);
        int src = (int)(pos & 31u);
        int widx = (pos < 32u) ? __shfl_sync(FULL, idx0, src)
                               : __shfl_sync(FULL, idx1, src);
        if (lane == it) { fkey = loc; fid = widx; }
        if (k0 == loc) k0 = 0u;
        if (k1 == loc) k1 = 0u;
    }

    float val = funmono(fkey & ~63u);
    float v0 = __shfl_sync(FULL, val, 0);
    float e = (lane < TOPK) ? expf(val - v0) : 0.f;
    float ssum = e;
    #pragma unroll
    for (int off = 4; off; off >>= 1) ssum += __shfl_xor_sync(FULL, ssum, off);
    if (lane < TOPK) {
        wts[(size_t)t * TOPK + lane]  = e / ssum;
        idxs[(size_t)t * TOPK + lane] = fid;
    }
}

// ================= gather + gate + residual (exact R6) =================
__global__ __launch_bounds__(256) void gather_kernel(
    const float* __restrict__ x, const float* __restrict__ values,
    const float* __restrict__ gate_w, const float* __restrict__ gate_b,
    const float* __restrict__ wts, const int* __restrict__ idxs,
    float* __restrict__ out)
{
    const int t = blockIdx.x;
    const int tid = threadIdx.x;
    const int lane = tid & 31, wid = tid >> 5;

    const float4* xr = (const float4*)(x + (size_t)t * D_MODEL);
    const float4* gw = (const float4*)gate_w;

    float4 xv = xr[tid];
    float4 gv = gw[tid];
    float p = xv.x * gv.x + xv.y * gv.y + xv.z * gv.z + xv.w * gv.w;
    #pragma unroll
    for (int off = 16; off; off >>= 1) p += __shfl_down_sync(0xffffffffu, p, off);

    __shared__ float red[8];
    __shared__ float sw[TOPK];
    __shared__ int   sid[TOPK];
    __shared__ float sg;
    if (lane == 0) red[wid] = p;
    if (tid >= 32 && tid < 32 + TOPK) {
        sw[tid - 32]  = wts[(size_t)t * TOPK + (tid - 32)];
        sid[tid - 32] = idxs[(size_t)t * TOPK + (tid - 32)];
    }
    __syncthreads();
    if (tid == 0) {
        float s = red[0];
        #pragma unroll
        for (int w = 1; w < 8; w++) s += red[w];
        sg = 1.f / (1.f + expf(-(s + gate_b[0])));
    }
    __syncthreads();
    const float g = sg;

    float4 acc = make_float4(0.f, 0.f, 0.f, 0.f);
    #pragma unroll
    for (int k = 0; k < TOPK; k++) {
        const float4* vr = (const float4*)(values + (size_t)sid[k] * D_MODEL);
        float4 vv = __ldg(vr + tid);
        float w = sw[k];
        acc.x += w * vv.x; acc.y += w * vv.y; acc.z += w * vv.z; acc.w += w * vv.w;
    }
    float4 o;
    o.x = xv.x + g * acc.x;
    o.y = xv.y + g * acc.y;
    o.z = xv.z + g * acc.z;
    o.w = xv.w + g * acc.w;
    ((float4*)(out + (size_t)t * D_MODEL))[tid] = o;
}

// ================= launch =================
extern "C" void kernel_launch(void* const* d_in, const int* in_sizes, int n_in,
                              void* d_out, int out_size)
{
    const float* x      = (const float*)d_in[0];
    const float* keys_a = (const float*)d_in[1];
    const float* keys_b = (const float*)d_in[2];
    const float* values = (const float*)d_in[3];
    const float* Wq     = (const float*)d_in[4];
    const float* gate_w = (const float*)d_in[5];
    const float* gate_b = (const float*)d_in[6];
    float* out = (float*)d_out;

    const int NT = in_sizes[0] / D_MODEL;   // 8192

    __nv_bfloat16 *xb, *wqb, *kbb;
    float *sbuf, *wbuf; int *ibuf;
    cudaGetSymbolAddress((void**)&xb,   g_xb);
    cudaGetSymbolAddress((void**)&wqb,  g_wqb);
    cudaGetSymbolAddress((void**)&kbb,  g_kb);
    cudaGetSymbolAddress((void**)&sbuf, g_scores);
    cudaGetSymbolAddress((void**)&wbuf, g_wts);
    cudaGetSymbolAddress((void**)&ibuf, g_idx);

    // 0) convert inputs to bf16
    {
        int X4 = NT * D_MODEL / 4;
        int total = X4 + (2 * D_KEY * D_MODEL) / 4 + 2 * (N_SUB * D_KEY) / 4;
        convert_kernel<<<(total + 255) / 256, 256>>>(
            (const float4*)x, (const float4*)Wq, (const float4*)keys_a, (const float4*)keys_b,
            (uint2*)xb, (uint2*)wqb, (uint2*)kbb, X4);
    }
    // 1+2) fused q-projection + scores (grid.y = half)
    {
        const int dsm = 114688;
        cudaFuncSetAttribute(fused_gemm, cudaFuncAttributeMaxDynamicSharedMemorySize, dsm);
        dim3 grid(NT / 128, 2);
        fused_gemm<<<grid, 256, dsm>>>(xb, wqb, kbb, sbuf);
    }
    // 3) top-k + softmax
    topk_warp<<<(NT + 7) / 8, 256>>>(sbuf, wbuf, ibuf, NT);
    // 4) gather + gate + residual
    gather_kernel<<<NT, 256>>>(x, values, gate_w, gate_b, wbuf, ibuf, out);
}

// round 12
// speedup vs baseline: 1.3286x; 1.0274x over previous
#include <cuda_runtime.h>
#include <cuda_bf16.h>
#include <math.h>

#define D_MODEL 1024
#define D_KEY   128
#define N_SUB   256
#define TOPK    8
#define MAXNT   8192

// -------- scratch (device globals) --------
__device__ __align__(128) __nv_bfloat16 g_xb [MAXNT * D_MODEL];
__device__ __align__(128) __nv_bfloat16 g_wqb[2 * D_KEY * D_MODEL];
__device__ __align__(128) __nv_bfloat16 g_kb [2 * N_SUB * D_KEY];
__device__ __align__(128) float g_scores[MAXNT * 2 * N_SUB];
__device__ float g_wts[MAXNT * TOPK];
__device__ int   g_idx[MAXNT * TOPK];

// ================= base-PTX helpers =================
__device__ __forceinline__ unsigned smem_u32(const void* p) {
    unsigned a;
    asm("{ .reg .u64 t; cvta.to.shared.u64 t, %1; cvt.u32.u64 %0, t; }" : "=r"(a) : "l"(p));
    return a;
}
__device__ __forceinline__ void cpa16(unsigned d, const void* s) {
    asm volatile("cp.async.cg.shared.global [%0], [%1], 16;" :: "r"(d), "l"(s));
}
__device__ __forceinline__ void cpcommit() { asm volatile("cp.async.commit_group;" ::: "memory"); }
template<int N> __device__ __forceinline__ void cpwait() {
    asm volatile("cp.async.wait_group %0;" :: "n"(N) : "memory");
}
__device__ __forceinline__ void ldsm4(unsigned addr, unsigned& r0, unsigned& r1,
                                      unsigned& r2, unsigned& r3) {
    asm volatile("ldmatrix.sync.aligned.m8n8.x4.shared.b16 {%0,%1,%2,%3}, [%4];"
                 : "=r"(r0), "=r"(r1), "=r"(r2), "=r"(r3) : "r"(addr));
}
__device__ __forceinline__ void mma16816(float* c, const unsigned* a, const unsigned* b) {
    asm volatile("mma.sync.aligned.m16n8k16.row.col.f32.bf16.bf16.f32 "
                 "{%0,%1,%2,%3}, {%4,%5,%6,%7}, {%8,%9}, {%0,%1,%2,%3};"
                 : "+f"(c[0]), "+f"(c[1]), "+f"(c[2]), "+f"(c[3])
                 : "r"(a[0]), "r"(a[1]), "r"(a[2]), "r"(a[3]), "r"(b[0]), "r"(b[1]));
}
__device__ __forceinline__ unsigned pk_bf16x2(float a, float b) {
    __nv_bfloat162 h = __floats2bfloat162_rn(a, b);
    return *(unsigned*)&h;
}
__device__ __forceinline__ unsigned fmono(float f) {
    unsigned u = __float_as_uint(f);
    return u ^ (((unsigned)((int)u >> 31)) | 0x80000000u);
}
__device__ __forceinline__ float funmono(unsigned m) {
    unsigned u = (m & 0x80000000u) ? (m ^ 0x80000000u) : ~m;
    return __uint_as_float(u);
}
__device__ __forceinline__ unsigned redux_max(unsigned v) {
    unsigned d;
    asm volatile("redux.sync.max.u32 %0, %1, 0xffffffff;" : "=r"(d) : "r"(v));
    return d;
}

// ================= convert fp32 -> bf16 (x, Wq, keys) =================
__global__ __launch_bounds__(256) void convert_kernel(
    const float4* __restrict__ x, const float4* __restrict__ wq,
    const float4* __restrict__ ka, const float4* __restrict__ kb,
    uint2* __restrict__ xb, uint2* __restrict__ wqb, uint2* __restrict__ kbb,
    int X4)
{
    const int W4 = (2 * D_KEY * D_MODEL) / 4;
    const int K4 = (N_SUB * D_KEY) / 4;
    int i = blockIdx.x * blockDim.x + threadIdx.x;
    float4 v; uint2 o;
    if (i < X4) {
        v = x[i];
        o.x = pk_bf16x2(v.x, v.y); o.y = pk_bf16x2(v.z, v.w);
        xb[i] = o;
    } else if (i < X4 + W4) {
        int j = i - X4; v = wq[j];
        o.x = pk_bf16x2(v.x, v.y); o.y = pk_bf16x2(v.z, v.w);
        wqb[j] = o;
    } else if (i < X4 + W4 + K4) {
        int j = i - X4 - W4; v = ka[j];
        o.x = pk_bf16x2(v.x, v.y); o.y = pk_bf16x2(v.z, v.w);
        kbb[j] = o;
    } else if (i < X4 + W4 + 2 * K4) {
        int j = i - X4 - W4 - K4; v = kb[j];
        o.x = pk_bf16x2(v.x, v.y); o.y = pk_bf16x2(v.z, v.w);
        kbb[K4 + j] = o;
    }
}

// ================= fused GEMM1+GEMM2, BK=64 =================
// Phase A: q tile [128x128] = xb[m0:,:] @ Wq_z^T, K=1024, 16 iters of BK=64,
//          3-stage cp.async; 128-byte smem rows, SW128 swizzle (chunk ^ (row&7)).
// Phase B: scores [128x256] = qtile @ keys_z^T, K=128; keys prefetched early.
// Smem: [0,98304) pipeline (A 16KB + B 16KB per stage x3); qtile reuses [0,32768);
//       [98304,163840) keys (2 chunks x 32KB).
__global__ __launch_bounds__(256) void fused_gemm(
    const __nv_bfloat16* __restrict__ Xb,
    const __nv_bfloat16* __restrict__ Wqb,
    const __nv_bfloat16* __restrict__ Keys,
    float* __restrict__ S)
{
    extern __shared__ __align__(128) char dsm[];
    const unsigned sbase = smem_u32(dsm);
    const unsigned KB = sbase + 98304u;

    const int tid = threadIdx.x, lane = tid & 31, wid = tid >> 5;
    const int m0 = blockIdx.x * 128;
    const int z  = blockIdx.y;

    const __nv_bfloat16* __restrict__ Ab = Xb + (size_t)m0 * D_MODEL;
    const __nv_bfloat16* __restrict__ Bb = Wqb + (size_t)(z * D_KEY) * D_MODEL;
    const __nv_bfloat16* __restrict__ Kz = Keys + (size_t)z * N_SUB * D_KEY;

    // ---------- phase A warp layout (64x32 warp tiles) ----------
    const int wmA = (wid & 1) * 64;
    const int wnA = (wid >> 1) * 32;
    const int rowA = wmA + (lane & 15);
    const unsigned aSwz = (unsigned)rowA & 7;
    const unsigned aBase = (unsigned)rowA * 128;
    const unsigned aSel = lane >> 4;           // 0/1
    const int rowB = wnA + (lane & 7) + ((lane >> 4) << 3);
    const unsigned bSwz = (unsigned)rowB & 7;
    const unsigned bBase = (unsigned)rowB * 128;
    const unsigned bSel = (lane >> 3) & 1;

    float acc[4][4][4];
    #pragma unroll
    for (int mt = 0; mt < 4; mt++)
        #pragma unroll
        for (int nt = 0; nt < 4; nt++)
            #pragma unroll
            for (int e = 0; e < 4; e++) acc[mt][nt][e] = 0.f;

    // fill one BK=64 stage: A 128x64 (16KB) + B 128x64 (16KB)
    auto fill = [&](int kt, int st) {
        const unsigned base = sbase + st * 32768u;
        const int kb = kt * 64;
        #pragma unroll
        for (int u = 0; u < 4; u++) {
            int idx = tid + u * 256;        // 0..1023
            int r = idx >> 3, c = idx & 7;
            unsigned soff = (unsigned)r * 128 + (((unsigned)c ^ ((unsigned)r & 7)) << 4);
            cpa16(base + soff,          Ab + (size_t)r * D_MODEL + kb + c * 8);
            cpa16(base + 16384u + soff, Bb + (size_t)r * D_MODEL + kb + c * 8);
        }
    };

    fill(0, 0); cpcommit();
    fill(1, 1); cpcommit();
    // keys prefetch: 256 rows x 2 chunks x 8 units (K=128 -> two 64-col chunks)
    #pragma unroll
    for (int i = 0; i < 16; i++) {
        int idx = tid + i * 256;            // 0..4095
        int c2 = idx >> 11;                 // 0..1
        int r  = (idx >> 3) & 255;
        int u  = idx & 7;
        cpa16(KB + (unsigned)c2 * 32768u + (unsigned)r * 128u +
                  ((((unsigned)u) ^ ((unsigned)r & 7)) << 4),
              Kz + (size_t)r * D_KEY + c2 * 64 + u * 8);
    }
    cpcommit();

    const int KT = 16;   // K=1024, BK=64
    for (int kt = 0; kt < KT; kt++) {
        cpwait<2>();
        __syncthreads();
        int pf = kt + 2;
        if (pf < KT) fill(pf, pf % 3);
        cpcommit();

        const unsigned As = sbase + (kt % 3) * 32768u;
        const unsigned Bs = As + 16384u;
        #pragma unroll
        for (int kk = 0; kk < 4; kk++) {
            unsigned a[4][4];
            #pragma unroll
            for (int mt = 0; mt < 4; mt++)
                ldsm4(As + aBase + mt * 2048u + ((((unsigned)(kk * 2) + aSel) ^ aSwz) << 4),
                      a[mt][0], a[mt][1], a[mt][2], a[mt][3]);
            unsigned b[4][2];
            #pragma unroll
            for (int g = 0; g < 2; g++) {
                unsigned r0, r1, r2, r3;
                ldsm4(Bs + bBase + g * 2048u + ((((unsigned)(kk * 2) + bSel) ^ bSwz) << 4),
                      r0, r1, r2, r3);
                b[g * 2][0] = r0; b[g * 2][1] = r1;
                b[g * 2 + 1][0] = r2; b[g * 2 + 1][1] = r3;
            }
            #pragma unroll
            for (int mt = 0; mt < 4; mt++)
                #pragma unroll
                for (int nt = 0; nt < 4; nt++)
                    mma16816(acc[mt][nt], a[mt], b[nt]);
        }
        __syncthreads();
    }

    // ---------- epilogue A: q tile -> smem [0,32768), 2 chunks of 128B rows ----------
    const int gid = lane >> 2;
    const int tg  = (lane & 3) * 2;
    #pragma unroll
    for (int mt = 0; mt < 4; mt++) {
        int r  = wmA + mt * 16 + gid;
        int r2 = r + 8;
        #pragma unroll
        for (int nt = 0; nt < 4; nt++) {
            int c = wnA + nt * 8 + tg;
            unsigned chunk = (unsigned)c >> 6, within = (unsigned)c & 63;
            unsigned u = within >> 3;
            unsigned byteoff0 = chunk * 16384u + (unsigned)r * 128u +
                                ((u ^ ((unsigned)r & 7)) << 4) + (within & 7) * 2;
            unsigned byteoff1 = chunk * 16384u + (unsigned)r2 * 128u +
                                ((u ^ ((unsigned)r2 & 7)) << 4) + (within & 7) * 2;
            *(unsigned*)(dsm + byteoff0) = pk_bf16x2(acc[mt][nt][0], acc[mt][nt][1]);
            *(unsigned*)(dsm + byteoff1) = pk_bf16x2(acc[mt][nt][2], acc[mt][nt][3]);
        }
    }
    cpwait<0>();      // keys resident
    __syncthreads();

    // ---------- phase B: scores = qtile @ keys_z^T (128x256, K=128) ----------
    const int wmB = (wid & 1) * 64;
    const int wnB = (wid >> 1) * 64;
    const int rowA2 = wmB + (lane & 15);
    const unsigned aSwz2 = (unsigned)rowA2 & 7;
    const unsigned aBase2 = (unsigned)rowA2 * 128;
    const int rowB2 = wnB + (lane & 7) + ((lane >> 4) << 3);
    const unsigned bSwz2 = (unsigned)rowB2 & 7;
    const unsigned bBase2 = (unsigned)rowB2 * 128;

    float acc2[4][8][4];
    #pragma unroll
    for (int mt = 0; mt < 4; mt++)
        #pragma unroll
        for (int nt = 0; nt < 8; nt++)
            #pragma unroll
            for (int e = 0; e < 4; e++) acc2[mt][nt][e] = 0.f;

    #pragma unroll
    for (int k = 0; k < 2; k++) {        // K chunks of 64
        const unsigned As = sbase + (unsigned)k * 16384u;
        const unsigned Bs = KB + (unsigned)k * 32768u;
        #pragma unroll
        for (int kk = 0; kk < 4; kk++) {
            unsigned a[4][4];
            #pragma unroll
            for (int mt = 0; mt < 4; mt++)
                ldsm4(As + aBase2 + mt * 2048u + ((((unsigned)(kk * 2) + aSel) ^ aSwz2) << 4),
                      a[mt][0], a[mt][1], a[mt][2], a[mt][3]);
            unsigned b[8][2];
            #pragma unroll
            for (int g = 0; g < 4; g++) {
                unsigned r0, r1, r2, r3;
                ldsm4(Bs + bBase2 + g * 2048u + ((((unsigned)(kk * 2) + bSel) ^ bSwz2) << 4),
                      r0, r1, r2, r3);
                b[g * 2][0] = r0; b[g * 2][1] = r1;
                b[g * 2 + 1][0] = r2; b[g * 2 + 1][1] = r3;
            }
            #pragma unroll
            for (int mt = 0; mt < 4; mt++)
                #pragma unroll
                for (int nt = 0; nt < 8; nt++)
                    mma16816(acc2[mt][nt], a[mt], b[nt]);
        }
    }

    // ---------- epilogue B: fp32 scores to gmem ----------
    #pragma unroll
    for (int mt = 0; mt < 4; mt++) {
        int r = m0 + wmB + mt * 16 + gid;
        #pragma unroll
        for (int nt = 0; nt < 8; nt++) {
            int col = z * N_SUB + wnB + nt * 8 + tg;
            *(float2*)(S + (size_t)r * (2 * N_SUB) + col)       = make_float2(acc2[mt][nt][0], acc2[mt][nt][1]);
            *(float2*)(S + (size_t)(r + 8) * (2 * N_SUB) + col) = make_float2(acc2[mt][nt][2], acc2[mt][nt][3]);
        }
    }
}

// ================= warp-per-token top-k (exact R6) =================
__global__ __launch_bounds__(256) void topk_warp(
    const float* __restrict__ scores,
    float* __restrict__ wts, int* __restrict__ idxs, int NT)
{
    const unsigned FULL = 0xffffffffu;
    const int lane = threadIdx.x & 31;
    const int t = blockIdx.x * 8 + (threadIdx.x >> 5);
    if (t >= NT) return;
    const float* row = scores + (size_t)t * (2 * N_SUB);

    unsigned ka[8], kb[8];
    {
        float4 p0 = *(const float4*)(row + lane * 8);
        float4 p1 = *(const float4*)(row + lane * 8 + 4);
        float4 q0 = *(const float4*)(row + 256 + lane * 8);
        float4 q1 = *(const float4*)(row + 256 + lane * 8 + 4);
        float fa[8] = {p0.x, p0.y, p0.z, p0.w, p1.x, p1.y, p1.z, p1.w};
        float fb[8] = {q0.x, q0.y, q0.z, q0.w, q1.x, q1.y, q1.z, q1.w};
        #pragma unroll
        for (int s = 0; s < 8; s++) {
            unsigned tag = 255u - (unsigned)(lane * 8 + s);
            ka[s] = (fmono(fa[s]) & 0xFFFFFF00u) | tag;
            kb[s] = (fmono(fb[s]) & 0xFFFFFF00u) | tag;
        }
    }

    unsigned myA = 0u, myB = 0u;
    #pragma unroll
    for (int it = 0; it < TOPK; it++) {
        unsigned la = ka[0], lb = kb[0];
        #pragma unroll
        for (int s = 1; s < 8; s++) { la = max(la, ka[s]); lb = max(lb, kb[s]); }
        unsigned wa = redux_max(la);
        unsigned wb = redux_max(lb);
        if (lane == it) { myA = wa; myB = wb; }
        #pragma unroll
        for (int s = 0; s < 8; s++) {
            if (ka[s] == wa) ka[s] = 0u;
            if (kb[s] == wb) kb[s] = 0u;
        }
    }

    unsigned a0k = __shfl_sync(FULL, myA, lane >> 3);
    unsigned a1k = __shfl_sync(FULL, myA, (lane >> 3) + 4);
    unsigned bk  = __shfl_sync(FULL, myB, lane & 7);
    float bvf = funmono(bk & 0xFFFFFF00u);
    float c0 = funmono(a0k & 0xFFFFFF00u) + bvf;
    float c1 = funmono(a1k & 0xFFFFFF00u) + bvf;
    int ib  = 255 - (int)(bk & 255u);
    int idx0 = (255 - (int)(a0k & 255u)) * N_SUB + ib;
    int idx1 = (255 - (int)(a1k & 255u)) * N_SUB + ib;
    unsigned k0 = (fmono(c0) & ~63u) | (63u - (unsigned)lane);
    unsigned k1 = (fmono(c1) & ~63u) | (63u - (unsigned)(lane + 32));

    unsigned fkey = 0u; int fid = 0;
    #pragma unroll
    for (int it = 0; it < TOPK; it++) {
        unsigned loc = redux_max(max(k0, k1));
        unsigned pos = 63u - (loc & 63u);
        int src = (int)(pos & 31u);
        int widx = (pos < 32u) ? __shfl_sync(FULL, idx0, src)
                               : __shfl_sync(FULL, idx1, src);
        if (lane == it) { fkey = loc; fid = widx; }
        if (k0 == loc) k0 = 0u;
        if (k1 == loc) k1 = 0u;
    }

    float val = funmono(fkey & ~63u);
    float v0 = __shfl_sync(FULL, val, 0);
    float e = (lane < TOPK) ? expf(val - v0) : 0.f;
    float ssum = e;
    #pragma unroll
    for (int off = 4; off; off >>= 1) ssum += __shfl_xor_sync(FULL, ssum, off);
    if (lane < TOPK) {
        wts[(size_t)t * TOPK + lane]  = e / ssum;
        idxs[(size_t)t * TOPK + lane] = fid;
    }
}

// ================= gather + gate + residual (exact R6) =================
__global__ __launch_bounds__(256) void gather_kernel(
    const float* __restrict__ x, const float* __restrict__ values,
    const float* __restrict__ gate_w, const float* __restrict__ gate_b,
    const float* __restrict__ wts, const int* __restrict__ idxs,
    float* __restrict__ out)
{
    const int t = blockIdx.x;
    const int tid = threadIdx.x;
    const int lane = tid & 31, wid = tid >> 5;

    const float4* xr = (const float4*)(x + (size_t)t * D_MODEL);
    const float4* gw = (const float4*)gate_w;

    float4 xv = xr[tid];
    float4 gv = gw[tid];
    float p = xv.x * gv.x + xv.y * gv.y + xv.z * gv.z + xv.w * gv.w;
    #pragma unroll
    for (int off = 16; off; off >>= 1) p += __shfl_down_sync(0xffffffffu, p, off);

    __shared__ float red[8];
    __shared__ float sw[TOPK];
    __shared__ int   sid[TOPK];
    __shared__ float sg;
    if (lane == 0) red[wid] = p;
    if (tid >= 32 && tid < 32 + TOPK) {
        sw[tid - 32]  = wts[(size_t)t * TOPK + (tid - 32)];
        sid[tid - 32] = idxs[(size_t)t * TOPK + (tid - 32)];
    }
    __syncthreads();
    if (tid == 0) {
        float s = red[0];
        #pragma unroll
        for (int w = 1; w < 8; w++) s += red[w];
        sg = 1.f / (1.f + expf(-(s + gate_b[0])));
    }
    __syncthreads();
    const float g = sg;

    float4 acc = make_float4(0.f, 0.f, 0.f, 0.f);
    #pragma unroll
    for (int k = 0; k < TOPK; k++) {
        const float4* vr = (const float4*)(values + (size_t)sid[k] * D_MODEL);
        float4 vv = __ldg(vr + tid);
        float w = sw[k];
        acc.x += w * vv.x; acc.y += w * vv.y; acc.z += w * vv.z; acc.w += w * vv.w;
    }
    float4 o;
    o.x = xv.x + g * acc.x;
    o.y = xv.y + g * acc.y;
    o.z = xv.z + g * acc.z;
    o.w = xv.w + g * acc.w;
    ((float4*)(out + (size_t)t * D_MODEL))[tid] = o;
}

// ================= launch =================
extern "C" void kernel_launch(void* const* d_in, const int* in_sizes, int n_in,
                              void* d_out, int out_size)
{
    const float* x      = (const float*)d_in[0];
    const float* keys_a = (const float*)d_in[1];
    const float* keys_b = (const float*)d_in[2];
    const float* values = (const float*)d_in[3];
    const float* Wq     = (const float*)d_in[4];
    const float* gate_w = (const float*)d_in[5];
    const float* gate_b = (const float*)d_in[6];
    float* out = (float*)d_out;

    const int NT = in_sizes[0] / D_MODEL;   // 8192

    __nv_bfloat16 *xb, *wqb, *kbb;
    float *sbuf, *wbuf; int *ibuf;
    cudaGetSymbolAddress((void**)&xb,   g_xb);
    cudaGetSymbolAddress((void**)&wqb,  g_wqb);
    cudaGetSymbolAddress((void**)&kbb,  g_kb);
    cudaGetSymbolAddress((void**)&sbuf, g_scores);
    cudaGetSymbolAddress((void**)&wbuf, g_wts);
    cudaGetSymbolAddress((void**)&ibuf, g_idx);

    // 0) convert inputs to bf16
    {
        int X4 = NT * D_MODEL / 4;
        int total = X4 + (2 * D_KEY * D_MODEL) / 4 + 2 * (N_SUB * D_KEY) / 4;
        convert_kernel<<<(total + 255) / 256, 256>>>(
            (const float4*)x, (const float4*)Wq, (const float4*)keys_a, (const float4*)keys_b,
            (uint2*)xb, (uint2*)wqb, (uint2*)kbb, X4);
    }
    // 1+2) fused q-projection + scores (grid.y = half), BK=64
    {
        const int dsm = 163840;
        cudaFuncSetAttribute(fused_gemm, cudaFuncAttributeMaxDynamicSharedMemorySize, dsm);
        dim3 grid(NT / 128, 2);
        fused_gemm<<<grid, 256, dsm>>>(xb, wqb, kbb, sbuf);
    }
    // 3) top-k + softmax
    topk_warp<<<(NT + 7) / 8, 256>>>(sbuf, wbuf, ibuf, NT);
    // 4) gather + gate + residual
    gather_kernel<<<NT, 256>>>(x, values, gate_w, gate_b, wbuf, ibuf, out);
}

// round 13
// speedup vs baseline: 1.3563x; 1.0208x over previous
#include <cuda_runtime.h>
#include <cuda_bf16.h>
#include <math.h>

#define D_MODEL 1024
#define D_KEY   128
#define N_SUB   256
#define TOPK    8
#define MAXNT   8192

// -------- scratch (device globals) --------
__device__ __align__(128) __nv_bfloat16 g_xb [MAXNT * D_MODEL];
__device__ __align__(128) __nv_bfloat16 g_wqb[2 * D_KEY * D_MODEL];
__device__ __align__(128) __nv_bfloat16 g_kb [2 * N_SUB * D_KEY];
__device__ __align__(128) float g_scores[MAXNT * 2 * N_SUB];
__device__ float g_wts[MAXNT * TOPK];
__device__ int   g_idx[MAXNT * TOPK];

// ================= base-PTX helpers =================
__device__ __forceinline__ unsigned smem_u32(const void* p) {
    unsigned a;
    asm("{ .reg .u64 t; cvta.to.shared.u64 t, %1; cvt.u32.u64 %0, t; }" : "=r"(a) : "l"(p));
    return a;
}
__device__ __forceinline__ void cpa16(unsigned d, const void* s) {
    asm volatile("cp.async.cg.shared.global [%0], [%1], 16;" :: "r"(d), "l"(s));
}
__device__ __forceinline__ void cpcommit() { asm volatile("cp.async.commit_group;" ::: "memory"); }
template<int N> __device__ __forceinline__ void cpwait() {
    asm volatile("cp.async.wait_group %0;" :: "n"(N) : "memory");
}
__device__ __forceinline__ void ldsm4(unsigned addr, unsigned& r0, unsigned& r1,
                                      unsigned& r2, unsigned& r3) {
    asm volatile("ldmatrix.sync.aligned.m8n8.x4.shared.b16 {%0,%1,%2,%3}, [%4];"
                 : "=r"(r0), "=r"(r1), "=r"(r2), "=r"(r3) : "r"(addr));
}
__device__ __forceinline__ void mma16816(float* c, const unsigned* a, const unsigned* b) {
    asm volatile("mma.sync.aligned.m16n8k16.row.col.f32.bf16.bf16.f32 "
                 "{%0,%1,%2,%3}, {%4,%5,%6,%7}, {%8,%9}, {%0,%1,%2,%3};"
                 : "+f"(c[0]), "+f"(c[1]), "+f"(c[2]), "+f"(c[3])
                 : "r"(a[0]), "r"(a[1]), "r"(a[2]), "r"(a[3]), "r"(b[0]), "r"(b[1]));
}
__device__ __forceinline__ unsigned pk_bf16x2(float a, float b) {
    __nv_bfloat162 h = __floats2bfloat162_rn(a, b);
    return *(unsigned*)&h;
}
__device__ __forceinline__ unsigned fmono(float f) {
    unsigned u = __float_as_uint(f);
    return u ^ (((unsigned)((int)u >> 31)) | 0x80000000u);
}
__device__ __forceinline__ float funmono(unsigned m) {
    unsigned u = (m & 0x80000000u) ? (m ^ 0x80000000u) : ~m;
    return __uint_as_float(u);
}
__device__ __forceinline__ unsigned redux_max(unsigned v) {
    unsigned d;
    asm volatile("redux.sync.max.u32 %0, %1, 0xffffffff;" : "=r"(d) : "r"(v));
    return d;
}

// ================= convert fp32 -> bf16 (x, Wq, keys) =================
__global__ __launch_bounds__(256) void convert_kernel(
    const float4* __restrict__ x, const float4* __restrict__ wq,
    const float4* __restrict__ ka, const float4* __restrict__ kb,
    uint2* __restrict__ xb, uint2* __restrict__ wqb, uint2* __restrict__ kbb,
    int X4)
{
    const int W4 = (2 * D_KEY * D_MODEL) / 4;
    const int K4 = (N_SUB * D_KEY) / 4;
    int i = blockIdx.x * blockDim.x + threadIdx.x;
    float4 v; uint2 o;
    if (i < X4) {
        v = x[i];
        o.x = pk_bf16x2(v.x, v.y); o.y = pk_bf16x2(v.z, v.w);
        xb[i] = o;
    } else if (i < X4 + W4) {
        int j = i - X4; v = wq[j];
        o.x = pk_bf16x2(v.x, v.y); o.y = pk_bf16x2(v.z, v.w);
        wqb[j] = o;
    } else if (i < X4 + W4 + K4) {
        int j = i - X4 - W4; v = ka[j];
        o.x = pk_bf16x2(v.x, v.y); o.y = pk_bf16x2(v.z, v.w);
        kbb[j] = o;
    } else if (i < X4 + W4 + 2 * K4) {
        int j = i - X4 - W4 - K4; v = kb[j];
        o.x = pk_bf16x2(v.x, v.y); o.y = pk_bf16x2(v.z, v.w);
        kbb[K4 + j] = o;
    }
}

// ================= fused GEMM1+GEMM2, BK=64 (exact R12) =================
__global__ __launch_bounds__(256) void fused_gemm(
    const __nv_bfloat16* __restrict__ Xb,
    const __nv_bfloat16* __restrict__ Wqb,
    const __nv_bfloat16* __restrict__ Keys,
    float* __restrict__ S)
{
    extern __shared__ __align__(128) char dsm[];
    const unsigned sbase = smem_u32(dsm);
    const unsigned KB = sbase + 98304u;

    const int tid = threadIdx.x, lane = tid & 31, wid = tid >> 5;
    const int m0 = blockIdx.x * 128;
    const int z  = blockIdx.y;

    const __nv_bfloat16* __restrict__ Ab = Xb + (size_t)m0 * D_MODEL;
    const __nv_bfloat16* __restrict__ Bb = Wqb + (size_t)(z * D_KEY) * D_MODEL;
    const __nv_bfloat16* __restrict__ Kz = Keys + (size_t)z * N_SUB * D_KEY;

    const int wmA = (wid & 1) * 64;
    const int wnA = (wid >> 1) * 32;
    const int rowA = wmA + (lane & 15);
    const unsigned aSwz = (unsigned)rowA & 7;
    const unsigned aBase = (unsigned)rowA * 128;
    const unsigned aSel = lane >> 4;
    const int rowB = wnA + (lane & 7) + ((lane >> 4) << 3);
    const unsigned bSwz = (unsigned)rowB & 7;
    const unsigned bBase = (unsigned)rowB * 128;
    const unsigned bSel = (lane >> 3) & 1;

    float acc[4][4][4];
    #pragma unroll
    for (int mt = 0; mt < 4; mt++)
        #pragma unroll
        for (int nt = 0; nt < 4; nt++)
            #pragma unroll
            for (int e = 0; e < 4; e++) acc[mt][nt][e] = 0.f;

    auto fill = [&](int kt, int st) {
        const unsigned base = sbase + st * 32768u;
        const int kb = kt * 64;
        #pragma unroll
        for (int u = 0; u < 4; u++) {
            int idx = tid + u * 256;
            int r = idx >> 3, c = idx & 7;
            unsigned soff = (unsigned)r * 128 + (((unsigned)c ^ ((unsigned)r & 7)) << 4);
            cpa16(base + soff,          Ab + (size_t)r * D_MODEL + kb + c * 8);
            cpa16(base + 16384u + soff, Bb + (size_t)r * D_MODEL + kb + c * 8);
        }
    };

    fill(0, 0); cpcommit();
    fill(1, 1); cpcommit();
    #pragma unroll
    for (int i = 0; i < 16; i++) {
        int idx = tid + i * 256;
        int c2 = idx >> 11;
        int r  = (idx >> 3) & 255;
        int u  = idx & 7;
        cpa16(KB + (unsigned)c2 * 32768u + (unsigned)r * 128u +
                  ((((unsigned)u) ^ ((unsigned)r & 7)) << 4),
              Kz + (size_t)r * D_KEY + c2 * 64 + u * 8);
    }
    cpcommit();

    const int KT = 16;
    for (int kt = 0; kt < KT; kt++) {
        cpwait<2>();
        __syncthreads();
        int pf = kt + 2;
        if (pf < KT) fill(pf, pf % 3);
        cpcommit();

        const unsigned As = sbase + (kt % 3) * 32768u;
        const unsigned Bs = As + 16384u;
        #pragma unroll
        for (int kk = 0; kk < 4; kk++) {
            unsigned a[4][4];
            #pragma unroll
            for (int mt = 0; mt < 4; mt++)
                ldsm4(As + aBase + mt * 2048u + ((((unsigned)(kk * 2) + aSel) ^ aSwz) << 4),
                      a[mt][0], a[mt][1], a[mt][2], a[mt][3]);
            unsigned b[4][2];
            #pragma unroll
            for (int g = 0; g < 2; g++) {
                unsigned r0, r1, r2, r3;
                ldsm4(Bs + bBase + g * 2048u + ((((unsigned)(kk * 2) + bSel) ^ bSwz) << 4),
                      r0, r1, r2, r3);
                b[g * 2][0] = r0; b[g * 2][1] = r1;
                b[g * 2 + 1][0] = r2; b[g * 2 + 1][1] = r3;
            }
            #pragma unroll
            for (int mt = 0; mt < 4; mt++)
                #pragma unroll
                for (int nt = 0; nt < 4; nt++)
                    mma16816(acc[mt][nt], a[mt], b[nt]);
        }
        __syncthreads();
    }

    const int gid = lane >> 2;
    const int tg  = (lane & 3) * 2;
    #pragma unroll
    for (int mt = 0; mt < 4; mt++) {
        int r  = wmA + mt * 16 + gid;
        int r2 = r + 8;
        #pragma unroll
        for (int nt = 0; nt < 4; nt++) {
            int c = wnA + nt * 8 + tg;
            unsigned chunk = (unsigned)c >> 6, within = (unsigned)c & 63;
            unsigned u = within >> 3;
            unsigned byteoff0 = chunk * 16384u + (unsigned)r * 128u +
                                ((u ^ ((unsigned)r & 7)) << 4) + (within & 7) * 2;
            unsigned byteoff1 = chunk * 16384u + (unsigned)r2 * 128u +
                                ((u ^ ((unsigned)r2 & 7)) << 4) + (within & 7) * 2;
            *(unsigned*)(dsm + byteoff0) = pk_bf16x2(acc[mt][nt][0], acc[mt][nt][1]);
            *(unsigned*)(dsm + byteoff1) = pk_bf16x2(acc[mt][nt][2], acc[mt][nt][3]);
        }
    }
    cpwait<0>();
    __syncthreads();

    const int wmB = (wid & 1) * 64;
    const int wnB = (wid >> 1) * 64;
    const int rowA2 = wmB + (lane & 15);
    const unsigned aSwz2 = (unsigned)rowA2 & 7;
    const unsigned aBase2 = (unsigned)rowA2 * 128;
    const int rowB2 = wnB + (lane & 7) + ((lane >> 4) << 3);
    const unsigned bSwz2 = (unsigned)rowB2 & 7;
    const unsigned bBase2 = (unsigned)rowB2 * 128;

    float acc2[4][8][4];
    #pragma unroll
    for (int mt = 0; mt < 4; mt++)
        #pragma unroll
        for (int nt = 0; nt < 8; nt++)
            #pragma unroll
            for (int e = 0; e < 4; e++) acc2[mt][nt][e] = 0.f;

    #pragma unroll
    for (int k = 0; k < 2; k++) {
        const unsigned As = sbase + (unsigned)k * 16384u;
        const unsigned Bs = KB + (unsigned)k * 32768u;
        #pragma unroll
        for (int kk = 0; kk < 4; kk++) {
            unsigned a[4][4];
            #pragma unroll
            for (int mt = 0; mt < 4; mt++)
                ldsm4(As + aBase2 + mt * 2048u + ((((unsigned)(kk * 2) + aSel) ^ aSwz2) << 4),
                      a[mt][0], a[mt][1], a[mt][2], a[mt][3]);
            unsigned b[8][2];
            #pragma unroll
            for (int g = 0; g < 4; g++) {
                unsigned r0, r1, r2, r3;
                ldsm4(Bs + bBase2 + g * 2048u + ((((unsigned)(kk * 2) + bSel) ^ bSwz2) << 4),
                      r0, r1, r2, r3);
                b[g * 2][0] = r0; b[g * 2][1] = r1;
                b[g * 2 + 1][0] = r2; b[g * 2 + 1][1] = r3;
            }
            #pragma unroll
            for (int mt = 0; mt < 4; mt++)
                #pragma unroll
                for (int nt = 0; nt < 8; nt++)
                    mma16816(acc2[mt][nt], a[mt], b[nt]);
        }
    }

    #pragma unroll
    for (int mt = 0; mt < 4; mt++) {
        int r = m0 + wmB + mt * 16 + gid;
        #pragma unroll
        for (int nt = 0; nt < 8; nt++) {
            int col = z * N_SUB + wnB + nt * 8 + tg;
            *(float2*)(S + (size_t)r * (2 * N_SUB) + col)       = make_float2(acc2[mt][nt][0], acc2[mt][nt][1]);
            *(float2*)(S + (size_t)(r + 8) * (2 * N_SUB) + col) = make_float2(acc2[mt][nt][2], acc2[mt][nt][3]);
        }
    }
}

// ================= top-k: 2 warps per token (half per warp) =================
// Block = 256 thr = 8 warps = 4 tokens. Warp (2j+h) computes half-h top-8 of
// token j; winners exchanged via smem; even warp combines + softmax + output.
__global__ __launch_bounds__(256) void topk_warp2(
    const float* __restrict__ scores,
    float* __restrict__ wts, int* __restrict__ idxs, int NT)
{
    const unsigned FULL = 0xffffffffu;
    const int tid = threadIdx.x;
    const int lane = tid & 31, wid = tid >> 5;
    const int tok = wid >> 1;           // 0..3
    const int h   = wid & 1;            // half
    const int t = blockIdx.x * 4 + tok;

    __shared__ unsigned cand[4][2][TOPK];

    if (t < NT) {
        const float* row = scores + (size_t)t * (2 * N_SUB) + h * N_SUB;
        unsigned ks[8];
        {
            float4 p0 = *(const float4*)(row + lane * 8);
            float4 p1 = *(const float4*)(row + lane * 8 + 4);
            float f[8] = {p0.x, p0.y, p0.z, p0.w, p1.x, p1.y, p1.z, p1.w};
            #pragma unroll
            for (int s = 0; s < 8; s++)
                ks[s] = (fmono(f[s]) & 0xFFFFFF00u) | (255u - (unsigned)(lane * 8 + s));
        }
        unsigned my = 0u;
        #pragma unroll
        for (int it = 0; it < TOPK; it++) {
            unsigned loc = ks[0];
            #pragma unroll
            for (int s = 1; s < 8; s++) loc = max(loc, ks[s]);
            unsigned w = redux_max(loc);
            if (lane == it) my = w;
            #pragma unroll
            for (int s = 0; s < 8; s++) if (ks[s] == w) ks[s] = 0u;
        }
        if (lane < TOPK) cand[tok][h][lane] = my;
    }
    __syncthreads();
    if (t >= NT || h) return;

    // even warp: combine 64 cartesian candidates
    unsigned a0k = cand[tok][0][lane >> 3];
    unsigned a1k = cand[tok][0][(lane >> 3) + 4];
    unsigned bk  = cand[tok][1][lane & 7];
    float bvf = funmono(bk & 0xFFFFFF00u);
    float c0 = funmono(a0k & 0xFFFFFF00u) + bvf;
    float c1 = funmono(a1k & 0xFFFFFF00u) + bvf;
    int ib  = 255 - (int)(bk & 255u);
    int idx0 = (255 - (int)(a0k & 255u)) * N_SUB + ib;
    int idx1 = (255 - (int)(a1k & 255u)) * N_SUB + ib;
    unsigned k0 = (fmono(c0) & ~63u) | (63u - (unsigned)lane);
    unsigned k1 = (fmono(c1) & ~63u) | (63u - (unsigned)(lane + 32));

    unsigned fkey = 0u; int fid = 0;
    #pragma unroll
    for (int it = 0; it < TOPK; it++) {
        unsigned loc = redux_max(max(k0, k1));
        unsigned pos = 63u - (loc & 63u);
        int src = (int)(pos & 31u);
        int widx = (pos < 32u) ? __shfl_sync(FULL, idx0, src)
                               : __shfl_sync(FULL, idx1, src);
        if (lane == it) { fkey = loc; fid = widx; }
        if (k0 == loc) k0 = 0u;
        if (k1 == loc) k1 = 0u;
    }

    float val = funmono(fkey & ~63u);
    float v0 = __shfl_sync(FULL, val, 0);
    float e = (lane < TOPK) ? expf(val - v0) : 0.f;
    float ssum = e;
    #pragma unroll
    for (int off = 4; off; off >>= 1) ssum += __shfl_xor_sync(FULL, ssum, off);
    if (lane < TOPK) {
        wts[(size_t)t * TOPK + lane]  = e / ssum;
        idxs[(size_t)t * TOPK + lane] = fid;
    }
}

// ================= gather + gate + residual: shfl-broadcast indices =================
__global__ __launch_bounds__(256) void gather_kernel(
    const float* __restrict__ x, const float* __restrict__ values,
    const float* __restrict__ gate_w, const float* __restrict__ gate_b,
    const float* __restrict__ wts, const int* __restrict__ idxs,
    float* __restrict__ out)
{
    const unsigned FULL = 0xffffffffu;
    const int t = blockIdx.x;
    const int tid = threadIdx.x;
    const int lane = tid & 31, wid = tid >> 5;

    // every warp loads wts/idx in lanes 0..15, broadcasts via shfl (no barrier
    // on the value-gather dependency chain)
    float wl = 0.f; int il = 0;
    if (lane < TOPK)            wl = wts[(size_t)t * TOPK + lane];
    else if (lane < 2 * TOPK)   il = idxs[(size_t)t * TOPK + (lane - TOPK)];
    float swv[TOPK]; int sidv[TOPK];
    #pragma unroll
    for (int k = 0; k < TOPK; k++) {
        swv[k]  = __shfl_sync(FULL, wl, k);
        sidv[k] = __shfl_sync(FULL, il, k + TOPK);
    }

    const float4* xr = (const float4*)(x + (size_t)t * D_MODEL);
    float4 xv = xr[tid];
    float4 gv = ((const float4*)gate_w)[tid];
    float p = xv.x * gv.x + xv.y * gv.y + xv.z * gv.z + xv.w * gv.w;
    #pragma unroll
    for (int off = 16; off; off >>= 1) p += __shfl_down_sync(FULL, p, off);

    __shared__ float red[8];
    if (lane == 0) red[wid] = p;

    // value gathers issue here — not blocked by the gate barrier
    float4 acc = make_float4(0.f, 0.f, 0.f, 0.f);
    #pragma unroll
    for (int k = 0; k < TOPK; k++) {
        const float4* vr = (const float4*)(values + (size_t)sidv[k] * D_MODEL);
        float4 vv = __ldg(vr + tid);
        float w = swv[k];
        acc.x += w * vv.x; acc.y += w * vv.y; acc.z += w * vv.z; acc.w += w * vv.w;
    }

    __syncthreads();
    float s = red[0] + red[1] + red[2] + red[3] + red[4] + red[5] + red[6] + red[7];
    const float g = 1.f / (1.f + expf(-(s + gate_b[0])));

    float4 o;
    o.x = xv.x + g * acc.x;
    o.y = xv.y + g * acc.y;
    o.z = xv.z + g * acc.z;
    o.w = xv.w + g * acc.w;
    ((float4*)(out + (size_t)t * D_MODEL))[tid] = o;
}

// ================= launch =================
extern "C" void kernel_launch(void* const* d_in, const int* in_sizes, int n_in,
                              void* d_out, int out_size)
{
    const float* x      = (const float*)d_in[0];
    const float* keys_a = (const float*)d_in[1];
    const float* keys_b = (const float*)d_in[2];
    const float* values = (const float*)d_in[3];
    const float* Wq     = (const float*)d_in[4];
    const float* gate_w = (const float*)d_in[5];
    const float* gate_b = (const float*)d_in[6];
    float* out = (float*)d_out;

    const int NT = in_sizes[0] / D_MODEL;   // 8192

    __nv_bfloat16 *xb, *wqb, *kbb;
    float *sbuf, *wbuf; int *ibuf;
    cudaGetSymbolAddress((void**)&xb,   g_xb);
    cudaGetSymbolAddress((void**)&wqb,  g_wqb);
    cudaGetSymbolAddress((void**)&kbb,  g_kb);
    cudaGetSymbolAddress((void**)&sbuf, g_scores);
    cudaGetSymbolAddress((void**)&wbuf, g_wts);
    cudaGetSymbolAddress((void**)&ibuf, g_idx);

    // 0) convert inputs to bf16
    {
        int X4 = NT * D_MODEL / 4;
        int total = X4 + (2 * D_KEY * D_MODEL) / 4 + 2 * (N_SUB * D_KEY) / 4;
        convert_kernel<<<(total + 255) / 256, 256>>>(
            (const float4*)x, (const float4*)Wq, (const float4*)keys_a, (const float4*)keys_b,
            (uint2*)xb, (uint2*)wqb, (uint2*)kbb, X4);
    }
    // 1+2) fused q-projection + scores (grid.y = half), BK=64
    {
        const int dsm = 163840;
        cudaFuncSetAttribute(fused_gemm, cudaFuncAttributeMaxDynamicSharedMemorySize, dsm);
        dim3 grid(NT / 128, 2);
        fused_gemm<<<grid, 256, dsm>>>(xb, wqb, kbb, sbuf);
    }
    // 3) top-k + softmax (2 warps/token)
    topk_warp2<<<(NT + 3) / 4, 256>>>(sbuf, wbuf, ibuf, NT);
    // 4) gather + gate + residual
    gather_kernel<<<NT, 256>>>(x, values, gate_w, gate_b, wbuf, ibuf, out);
}

// round 14
// speedup vs baseline: 1.3936x; 1.0276x over previous
#include <cuda_runtime.h>
#include <cuda_bf16.h>
#include <math.h>

#define D_MODEL 1024
#define D_KEY   128
#define N_SUB   256
#define TOPK    8
#define MAXNT   8192
#define SC_LD   260

// -------- scratch (device globals) --------
__device__ __align__(128) __nv_bfloat16 g_xb [MAXNT * D_MODEL];
__device__ __align__(128) __nv_bfloat16 g_wqb[2 * D_KEY * D_MODEL];
__device__ __align__(128) __nv_bfloat16 g_kb [2 * N_SUB * D_KEY];
__device__ __align__(128) unsigned g_cand[MAXNT * 16];

// ================= base-PTX helpers =================
__device__ __forceinline__ unsigned smem_u32(const void* p) {
    unsigned a;
    asm("{ .reg .u64 t; cvta.to.shared.u64 t, %1; cvt.u32.u64 %0, t; }" : "=r"(a) : "l"(p));
    return a;
}
__device__ __forceinline__ void cpa16(unsigned d, const void* s) {
    asm volatile("cp.async.cg.shared.global [%0], [%1], 16;" :: "r"(d), "l"(s));
}
__device__ __forceinline__ void cpcommit() { asm volatile("cp.async.commit_group;" ::: "memory"); }
template<int N> __device__ __forceinline__ void cpwait() {
    asm volatile("cp.async.wait_group %0;" :: "n"(N) : "memory");
}
__device__ __forceinline__ void ldsm4(unsigned addr, unsigned& r0, unsigned& r1,
                                      unsigned& r2, unsigned& r3) {
    asm volatile("ldmatrix.sync.aligned.m8n8.x4.shared.b16 {%0,%1,%2,%3}, [%4];"
                 : "=r"(r0), "=r"(r1), "=r"(r2), "=r"(r3) : "r"(addr));
}
__device__ __forceinline__ void mma16816(float* c, const unsigned* a, const unsigned* b) {
    asm volatile("mma.sync.aligned.m16n8k16.row.col.f32.bf16.bf16.f32 "
                 "{%0,%1,%2,%3}, {%4,%5,%6,%7}, {%8,%9}, {%0,%1,%2,%3};"
                 : "+f"(c[0]), "+f"(c[1]), "+f"(c[2]), "+f"(c[3])
                 : "r"(a[0]), "r"(a[1]), "r"(a[2]), "r"(a[3]), "r"(b[0]), "r"(b[1]));
}
__device__ __forceinline__ unsigned pk_bf16x2(float a, float b) {
    __nv_bfloat162 h = __floats2bfloat162_rn(a, b);
    return *(unsigned*)&h;
}
__device__ __forceinline__ unsigned fmono(float f) {
    unsigned u = __float_as_uint(f);
    return u ^ (((unsigned)((int)u >> 31)) | 0x80000000u);
}
__device__ __forceinline__ float funmono(unsigned m) {
    unsigned u = (m & 0x80000000u) ? (m ^ 0x80000000u) : ~m;
    return __uint_as_float(u);
}
__device__ __forceinline__ unsigned redux_max(unsigned v) {
    unsigned d;
    asm volatile("redux.sync.max.u32 %0, %1, 0xffffffff;" : "=r"(d) : "r"(v));
    return d;
}

// ================= convert fp32 -> bf16 (x, Wq, keys) =================
__global__ __launch_bounds__(256) void convert_kernel(
    const float4* __restrict__ x, const float4* __restrict__ wq,
    const float4* __restrict__ ka, const float4* __restrict__ kb,
    uint2* __restrict__ xb, uint2* __restrict__ wqb, uint2* __restrict__ kbb,
    int X4)
{
    const int W4 = (2 * D_KEY * D_MODEL) / 4;
    const int K4 = (N_SUB * D_KEY) / 4;
    int i = blockIdx.x * blockDim.x + threadIdx.x;
    float4 v; uint2 o;
    if (i < X4) {
        v = x[i];
        o.x = pk_bf16x2(v.x, v.y); o.y = pk_bf16x2(v.z, v.w);
        xb[i] = o;
    } else if (i < X4 + W4) {
        int j = i - X4; v = wq[j];
        o.x = pk_bf16x2(v.x, v.y); o.y = pk_bf16x2(v.z, v.w);
        wqb[j] = o;
    } else if (i < X4 + W4 + K4) {
        int j = i - X4 - W4; v = ka[j];
        o.x = pk_bf16x2(v.x, v.y); o.y = pk_bf16x2(v.z, v.w);
        kbb[j] = o;
    } else if (i < X4 + W4 + 2 * K4) {
        int j = i - X4 - W4 - K4; v = kb[j];
        o.x = pk_bf16x2(v.x, v.y); o.y = pk_bf16x2(v.z, v.w);
        kbb[K4 + j] = o;
    }
}

// ================= fused GEMM1+GEMM2+half-top8, BK=64 =================
// Phase A (R12): q tile [128x128], K=1024. Phase B (R12): scores 128x256.
// Epilogue: acc2 -> smem score buffer [128][SC_LD] -> per-warp top-8 over
// 16 rows (2-row interleaved redux chains) -> 8 packed candidates per row.
__global__ __launch_bounds__(256) void fused_gemm(
    const __nv_bfloat16* __restrict__ Xb,
    const __nv_bfloat16* __restrict__ Wqb,
    const __nv_bfloat16* __restrict__ Keys,
    unsigned* __restrict__ cand)
{
    extern __shared__ __align__(128) char dsm[];
    const unsigned sbase = smem_u32(dsm);
    const unsigned KB = sbase + 98304u;

    const int tid = threadIdx.x, lane = tid & 31, wid = tid >> 5;
    const int m0 = blockIdx.x * 128;
    const int z  = blockIdx.y;

    const __nv_bfloat16* __restrict__ Ab = Xb + (size_t)m0 * D_MODEL;
    const __nv_bfloat16* __restrict__ Bb = Wqb + (size_t)(z * D_KEY) * D_MODEL;
    const __nv_bfloat16* __restrict__ Kz = Keys + (size_t)z * N_SUB * D_KEY;

    const int wmA = (wid & 1) * 64;
    const int wnA = (wid >> 1) * 32;
    const int rowA = wmA + (lane & 15);
    const unsigned aSwz = (unsigned)rowA & 7;
    const unsigned aBase = (unsigned)rowA * 128;
    const unsigned aSel = lane >> 4;
    const int rowB = wnA + (lane & 7) + ((lane >> 4) << 3);
    const unsigned bSwz = (unsigned)rowB & 7;
    const unsigned bBase = (unsigned)rowB * 128;
    const unsigned bSel = (lane >> 3) & 1;

    float acc[4][4][4];
    #pragma unroll
    for (int mt = 0; mt < 4; mt++)
        #pragma unroll
        for (int nt = 0; nt < 4; nt++)
            #pragma unroll
            for (int e = 0; e < 4; e++) acc[mt][nt][e] = 0.f;

    auto fill = [&](int kt, int st) {
        const unsigned base = sbase + st * 32768u;
        const int kb = kt * 64;
        #pragma unroll
        for (int u = 0; u < 4; u++) {
            int idx = tid + u * 256;
            int r = idx >> 3, c = idx & 7;
            unsigned soff = (unsigned)r * 128 + (((unsigned)c ^ ((unsigned)r & 7)) << 4);
            cpa16(base + soff,          Ab + (size_t)r * D_MODEL + kb + c * 8);
            cpa16(base + 16384u + soff, Bb + (size_t)r * D_MODEL + kb + c * 8);
        }
    };

    fill(0, 0); cpcommit();
    fill(1, 1); cpcommit();
    #pragma unroll
    for (int i = 0; i < 16; i++) {
        int idx = tid + i * 256;
        int c2 = idx >> 11;
        int r  = (idx >> 3) & 255;
        int u  = idx & 7;
        cpa16(KB + (unsigned)c2 * 32768u + (unsigned)r * 128u +
                  ((((unsigned)u) ^ ((unsigned)r & 7)) << 4),
              Kz + (size_t)r * D_KEY + c2 * 64 + u * 8);
    }
    cpcommit();

    const int KT = 16;
    for (int kt = 0; kt < KT; kt++) {
        cpwait<2>();
        __syncthreads();
        int pf = kt + 2;
        if (pf < KT) fill(pf, pf % 3);
        cpcommit();

        const unsigned As = sbase + (kt % 3) * 32768u;
        const unsigned Bs = As + 16384u;
        #pragma unroll
        for (int kk = 0; kk < 4; kk++) {
            unsigned a[4][4];
            #pragma unroll
            for (int mt = 0; mt < 4; mt++)
                ldsm4(As + aBase + mt * 2048u + ((((unsigned)(kk * 2) + aSel) ^ aSwz) << 4),
                      a[mt][0], a[mt][1], a[mt][2], a[mt][3]);
            unsigned b[4][2];
            #pragma unroll
            for (int g = 0; g < 2; g++) {
                unsigned r0, r1, r2, r3;
                ldsm4(Bs + bBase + g * 2048u + ((((unsigned)(kk * 2) + bSel) ^ bSwz) << 4),
                      r0, r1, r2, r3);
                b[g * 2][0] = r0; b[g * 2][1] = r1;
                b[g * 2 + 1][0] = r2; b[g * 2 + 1][1] = r3;
            }
            #pragma unroll
            for (int mt = 0; mt < 4; mt++)
                #pragma unroll
                for (int nt = 0; nt < 4; nt++)
                    mma16816(acc[mt][nt], a[mt], b[nt]);
        }
        __syncthreads();
    }

    // ---------- epilogue A: q tile -> smem [0,32768) ----------
    const int gid = lane >> 2;
    const int tg  = (lane & 3) * 2;
    #pragma unroll
    for (int mt = 0; mt < 4; mt++) {
        int r  = wmA + mt * 16 + gid;
        int r2 = r + 8;
        #pragma unroll
        for (int nt = 0; nt < 4; nt++) {
            int c = wnA + nt * 8 + tg;
            unsigned chunk = (unsigned)c >> 6, within = (unsigned)c & 63;
            unsigned u = within >> 3;
            unsigned byteoff0 = chunk * 16384u + (unsigned)r * 128u +
                                ((u ^ ((unsigned)r & 7)) << 4) + (within & 7) * 2;
            unsigned byteoff1 = chunk * 16384u + (unsigned)r2 * 128u +
                                ((u ^ ((unsigned)r2 & 7)) << 4) + (within & 7) * 2;
            *(unsigned*)(dsm + byteoff0) = pk_bf16x2(acc[mt][nt][0], acc[mt][nt][1]);
            *(unsigned*)(dsm + byteoff1) = pk_bf16x2(acc[mt][nt][2], acc[mt][nt][3]);
        }
    }
    cpwait<0>();
    __syncthreads();

    // ---------- phase B: scores = qtile @ keys_z^T (128x256, K=128) ----------
    const int wmB = (wid & 1) * 64;
    const int wnB = (wid >> 1) * 64;
    const int rowA2 = wmB + (lane & 15);
    const unsigned aSwz2 = (unsigned)rowA2 & 7;
    const unsigned aBase2 = (unsigned)rowA2 * 128;
    const int rowB2 = wnB + (lane & 7) + ((lane >> 4) << 3);
    const unsigned bSwz2 = (unsigned)rowB2 & 7;
    const unsigned bBase2 = (unsigned)rowB2 * 128;

    float acc2[4][8][4];
    #pragma unroll
    for (int mt = 0; mt < 4; mt++)
        #pragma unroll
        for (int nt = 0; nt < 8; nt++)
            #pragma unroll
            for (int e = 0; e < 4; e++) acc2[mt][nt][e] = 0.f;

    #pragma unroll
    for (int k = 0; k < 2; k++) {
        const unsigned As = sbase + (unsigned)k * 16384u;
        const unsigned Bs = KB + (unsigned)k * 32768u;
        #pragma unroll
        for (int kk = 0; kk < 4; kk++) {
            unsigned a[4][4];
            #pragma unroll
            for (int mt = 0; mt < 4; mt++)
                ldsm4(As + aBase2 + mt * 2048u + ((((unsigned)(kk * 2) + aSel) ^ aSwz2) << 4),
                      a[mt][0], a[mt][1], a[mt][2], a[mt][3]);
            unsigned b[8][2];
            #pragma unroll
            for (int g = 0; g < 4; g++) {
                unsigned r0, r1, r2, r3;
                ldsm4(Bs + bBase2 + g * 2048u + ((((unsigned)(kk * 2) + bSel) ^ bSwz2) << 4),
                      r0, r1, r2, r3);
                b[g * 2][0] = r0; b[g * 2][1] = r1;
                b[g * 2 + 1][0] = r2; b[g * 2 + 1][1] = r3;
            }
            #pragma unroll
            for (int mt = 0; mt < 4; mt++)
                #pragma unroll
                for (int nt = 0; nt < 8; nt++)
                    mma16816(acc2[mt][nt], a[mt], b[nt]);
        }
    }

    // ---------- epilogue B: scores -> smem, then per-warp top-8 ----------
    __syncthreads();                       // all ldsm reads done; smem reusable
    float* sc = (float*)dsm;
    #pragma unroll
    for (int mt = 0; mt < 4; mt++) {
        int r = wmB + mt * 16 + gid;
        #pragma unroll
        for (int nt = 0; nt < 8; nt++) {
            int col = wnB + nt * 8 + tg;
            *(float2*)&sc[(size_t)r * SC_LD + col]       = make_float2(acc2[mt][nt][0], acc2[mt][nt][1]);
            *(float2*)&sc[(size_t)(r + 8) * SC_LD + col] = make_float2(acc2[mt][nt][2], acc2[mt][nt][3]);
        }
    }
    __syncthreads();

    // per-warp top-8, two rows interleaved per pass
    for (int j = 0; j < 8; j++) {
        const int r0 = wid * 16 + j;
        const int r1 = r0 + 8;
        unsigned k0[8], k1[8];
        #pragma unroll
        for (int s = 0; s < 8; s++) {
            unsigned tag = 255u - (unsigned)(s * 32 + lane);
            k0[s] = (fmono(sc[(size_t)r0 * SC_LD + s * 32 + lane]) & 0xFFFFFF00u) | tag;
            k1[s] = (fmono(sc[(size_t)r1 * SC_LD + s * 32 + lane]) & 0xFFFFFF00u) | tag;
        }
        unsigned my0 = 0u, my1 = 0u;
        #pragma unroll
        for (int it = 0; it < TOPK; it++) {
            unsigned l0 = k0[0], l1 = k1[0];
            #pragma unroll
            for (int s = 1; s < 8; s++) { l0 = max(l0, k0[s]); l1 = max(l1, k1[s]); }
            unsigned w0 = redux_max(l0);
            unsigned w1 = redux_max(l1);
            if (lane == it) { my0 = w0; my1 = w1; }
            #pragma unroll
            for (int s = 0; s < 8; s++) {
                if (k0[s] == w0) k0[s] = 0u;
                if (k1[s] == w1) k1[s] = 0u;
            }
        }
        if (lane < TOPK) {
            cand[(size_t)(m0 + r0) * 16 + z * 8 + lane] = my0;
            cand[(size_t)(m0 + r1) * 16 + z * 8 + lane] = my1;
        }
    }
}

// ================= gather + combine + softmax + gate + residual =================
// Each warp redundantly combines the 16 candidates (64B, cached) via redux;
// no barrier on the value-gather chain.
__global__ __launch_bounds__(256) void gather_kernel(
    const unsigned* __restrict__ cand,
    const float* __restrict__ x, const float* __restrict__ values,
    const float* __restrict__ gate_w, const float* __restrict__ gate_b,
    float* __restrict__ out)
{
    const unsigned FULL = 0xffffffffu;
    const int t = blockIdx.x;
    const int tid = threadIdx.x;
    const int lane = tid & 31, wid = tid >> 5;

    // independent loads first: x + gate_w
    const float4* xr = (const float4*)(x + (size_t)t * D_MODEL);
    float4 xv = xr[tid];
    float4 gv = ((const float4*)gate_w)[tid];

    // ---- combine 64 cartesian candidates (redundant per warp) ----
    const unsigned* c = cand + (size_t)t * 16;
    unsigned a0k = __ldg(c + (lane >> 3));
    unsigned a1k = __ldg(c + (lane >> 3) + 4);
    unsigned bk  = __ldg(c + 8 + (lane & 7));
    float bvf = funmono(bk & 0xFFFFFF00u);
    float c0 = funmono(a0k & 0xFFFFFF00u) + bvf;
    float c1 = funmono(a1k & 0xFFFFFF00u) + bvf;
    int ib  = 255 - (int)(bk & 255u);
    int idx0 = (255 - (int)(a0k & 255u)) * N_SUB + ib;
    int idx1 = (255 - (int)(a1k & 255u)) * N_SUB + ib;
    unsigned k0 = (fmono(c0) & ~63u) | (63u - (unsigned)lane);
    unsigned k1 = (fmono(c1) & ~63u) | (63u - (unsigned)(lane + 32));

    unsigned fkey = 0u; int fid = 0;
    #pragma unroll
    for (int it = 0; it < TOPK; it++) {
        unsigned loc = redux_max(max(k0, k1));
        unsigned pos = 63u - (loc & 63u);
        int src = (int)(pos & 31u);
        int widx = (pos < 32u) ? __shfl_sync(FULL, idx0, src)
                               : __shfl_sync(FULL, idx1, src);
        if (lane == it) { fkey = loc; fid = widx; }
        if (k0 == loc) k0 = 0u;
        if (k1 == loc) k1 = 0u;
    }

    float val = funmono(fkey & ~63u);
    float v0 = __shfl_sync(FULL, val, 0);
    float e = (lane < TOPK) ? expf(val - v0) : 0.f;
    float ssum = e;
    #pragma unroll
    for (int off = 4; off; off >>= 1) ssum += __shfl_xor_sync(FULL, ssum, off);
    float wk = e / ssum;

    float swv[TOPK]; int sidv[TOPK];
    #pragma unroll
    for (int k = 0; k < TOPK; k++) {
        swv[k]  = __shfl_sync(FULL, wk, k);
        sidv[k] = __shfl_sync(FULL, fid, k);
    }

    // ---- gate partial (overlaps with value gathers below) ----
    float p = xv.x * gv.x + xv.y * gv.y + xv.z * gv.z + xv.w * gv.w;
    #pragma unroll
    for (int off = 16; off; off >>= 1) p += __shfl_down_sync(FULL, p, off);
    __shared__ float red[8];
    if (lane == 0) red[wid] = p;

    // ---- value gathers ----
    float4 acc = make_float4(0.f, 0.f, 0.f, 0.f);
    #pragma unroll
    for (int k = 0; k < TOPK; k++) {
        const float4* vr = (const float4*)(values + (size_t)sidv[k] * D_MODEL);
        float4 vv = __ldg(vr + tid);
        float w = swv[k];
        acc.x += w * vv.x; acc.y += w * vv.y; acc.z += w * vv.z; acc.w += w * vv.w;
    }

    __syncthreads();
    float s = red[0] + red[1] + red[2] + red[3] + red[4] + red[5] + red[6] + red[7];
    const float g = 1.f / (1.f + expf(-(s + gate_b[0])));

    float4 o;
    o.x = xv.x + g * acc.x;
    o.y = xv.y + g * acc.y;
    o.z = xv.z + g * acc.z;
    o.w = xv.w + g * acc.w;
    ((float4*)(out + (size_t)t * D_MODEL))[tid] = o;
}

// ================= launch =================
extern "C" void kernel_launch(void* const* d_in, const int* in_sizes, int n_in,
                              void* d_out, int out_size)
{
    const float* x      = (const float*)d_in[0];
    const float* keys_a = (const float*)d_in[1];
    const float* keys_b = (const float*)d_in[2];
    const float* values = (const float*)d_in[3];
    const float* Wq     = (const float*)d_in[4];
    const float* gate_w = (const float*)d_in[5];
    const float* gate_b = (const float*)d_in[6];
    float* out = (float*)d_out;

    const int NT = in_sizes[0] / D_MODEL;   // 8192

    __nv_bfloat16 *xb, *wqb, *kbb;
    unsigned* cbuf;
    cudaGetSymbolAddress((void**)&xb,   g_xb);
    cudaGetSymbolAddress((void**)&wqb,  g_wqb);
    cudaGetSymbolAddress((void**)&kbb,  g_kb);
    cudaGetSymbolAddress((void**)&cbuf, g_cand);

    // 0) convert inputs to bf16
    {
        int X4 = NT * D_MODEL / 4;
        int total = X4 + (2 * D_KEY * D_MODEL) / 4 + 2 * (N_SUB * D_KEY) / 4;
        convert_kernel<<<(total + 255) / 256, 256>>>(
            (const float4*)x, (const float4*)Wq, (const float4*)keys_a, (const float4*)keys_b,
            (uint2*)xb, (uint2*)wqb, (uint2*)kbb, X4);
    }
    // 1) fused q-projection + scores + per-half top-8
    {
        const int dsm = 163840;   // >= max(pipeline 98304 + keys 65536, 128*260*4)
        cudaFuncSetAttribute(fused_gemm, cudaFuncAttributeMaxDynamicSharedMemorySize, dsm);
        dim3 grid(NT / 128, 2);
        fused_gemm<<<grid, 256, dsm>>>(xb, wqb, kbb, cbuf);
    }
    // 2) combine + softmax + gather + gate + residual
    gather_kernel<<<NT, 256>>>(cbuf, x, values, gate_w, gate_b, out);
}